// round 13
// baseline (speedup 1.0000x reference)
#include <cuda_runtime.h>
#include <cuda_fp16.h>
#include <cstdint>
#include <math.h>

#define D_MODEL   2048
#define NUM_HEADS 16
#define HEAD_DIM  128
#define BATCH     2
#define SEQ       2048
#define M_TOTAL   (BATCH * SEQ)   // 4096

// ---------------- scratch (static device globals: no allocation allowed) ----
__device__ __half g_xh[M_TOTAL * D_MODEL];
__device__ __half g_xl[M_TOTAL * D_MODEL];
__device__ __half g_wqh[D_MODEL * D_MODEL];
__device__ __half g_wkh[D_MODEL * D_MODEL];
__device__ __half g_wvh[D_MODEL * D_MODEL];
__device__ __half g_woh[D_MODEL * D_MODEL];
__device__ __half g_Qh[M_TOTAL * D_MODEL];
__device__ __half g_Ql[M_TOTAL * D_MODEL];
__device__ __half g_Kh[M_TOTAL * D_MODEL];
__device__ __half g_Vh[M_TOTAL * D_MODEL];
__device__ __half g_Ch[M_TOTAL * D_MODEL];

// ============================================================================
// helpers
// ============================================================================
__device__ __forceinline__ uint32_t smem_u32(const void* p) {
    uint32_t a;
    asm("{ .reg .u64 t; cvta.to.shared.u64 t, %1; cvt.u32.u64 %0, t; }"
        : "=r"(a) : "l"(p));
    return a;
}
#define SW128(o) ((o) ^ (((o) >> 3) & 0x70))

__device__ __forceinline__ void ldsm4(uint32_t* r, uint32_t addr) {
    asm volatile("ldmatrix.sync.aligned.m8n8.x4.shared.b16 {%0,%1,%2,%3}, [%4];"
                 : "=r"(r[0]), "=r"(r[1]), "=r"(r[2]), "=r"(r[3]) : "r"(addr));
}
__device__ __forceinline__ void ldsm4t(uint32_t* r, uint32_t addr) {
    asm volatile("ldmatrix.sync.aligned.m8n8.x4.trans.shared.b16 {%0,%1,%2,%3}, [%4];"
                 : "=r"(r[0]), "=r"(r[1]), "=r"(r[2]), "=r"(r[3]) : "r"(addr));
}
__device__ __forceinline__ void mma16816(float* d, const uint32_t* a,
                                         const uint32_t* b) {
    asm volatile(
        "mma.sync.aligned.m16n8k16.row.col.f32.f16.f16.f32 "
        "{%0,%1,%2,%3}, {%4,%5,%6,%7}, {%8,%9}, {%0,%1,%2,%3};"
        : "+f"(d[0]), "+f"(d[1]), "+f"(d[2]), "+f"(d[3])
        : "r"(a[0]), "r"(a[1]), "r"(a[2]), "r"(a[3]), "r"(b[0]), "r"(b[1]));
}
__device__ __forceinline__ void cpasync16(uint32_t dst, const void* src) {
    asm volatile("cp.async.cg.shared.global [%0], [%1], 16;"
                 :: "r"(dst), "l"(src) : "memory");
}
#define CP_COMMIT() asm volatile("cp.async.commit_group;" ::: "memory")
#define CP_WAIT1()  asm volatile("cp.async.wait_group 1;" ::: "memory")
#define CP_WAIT0()  asm volatile("cp.async.wait_group 0;" ::: "memory")

// fp32 pair -> fp16x2 hi + fp16x2 lo (residual)
__device__ __forceinline__ void split2h(float a, float b, uint32_t& hi, uint32_t& lo) {
    __half2 h = __floats2half2_rn(a, b);
    hi = *(uint32_t*)&h;
    float ra = a - __half2float(h.x);
    float rb = b - __half2float(h.y);
    __half2 l = __floats2half2_rn(ra, rb);
    lo = *(uint32_t*)&l;
}
__device__ __forceinline__ uint32_t pack2h(float a, float b) {
    __half2 h = __floats2half2_rn(a, b);
    return *(uint32_t*)&h;
}

// fast 2^y on the FMA/ALU pipes (no MUFU). y <= ~0; -inf -> 0.
__device__ __forceinline__ float fexp2(float y) {
    y = fmaxf(y, -120.f);
    const float t = y + 12582912.f;          // 1.5*2^23: round(y) in mantissa
    const int   i = __float_as_int(t);
    const float f = y - (t - 12582912.f);    // f in [-0.5, 0.5]
    float p = 1.33335581e-3f;
    p = fmaf(p, f, 9.61812910e-3f);
    p = fmaf(p, f, 5.55041087e-2f);
    p = fmaf(p, f, 2.40226507e-1f);
    p = fmaf(p, f, 6.93147181e-1f);
    p = fmaf(p, f, 1.0f);
    return __int_as_float(__float_as_int(p) + (i << 23));
}

// ============================================================================
// prep: weight rounding (y=0..3) + x hi/lo split (y=4,5), one launch
// ============================================================================
__global__ __launch_bounds__(256)
void prep_kernel(const float4* __restrict__ x,
                 const float4* __restrict__ wq, const float4* __restrict__ wk,
                 const float4* __restrict__ wv, const float4* __restrict__ wo,
                 uint2* xh, uint2* xl, uint2* qh, uint2* kh, uint2* vh, uint2* oh,
                 int nw4)
{
    int i = blockIdx.x * blockDim.x + threadIdx.x;
    if (i >= nw4) return;
    const int y = blockIdx.y;
    if (y < 4) {
        const float4* s; uint2* h;
        switch (y) {
            case 0:  s = wq; h = qh; break;
            case 1:  s = wk; h = kh; break;
            case 2:  s = wv; h = vh; break;
            default: s = wo; h = oh; break;
        }
        float4 v = s[i];
        uint2 ho;
        ho.x = pack2h(v.x, v.y);
        ho.y = pack2h(v.z, v.w);
        h[i] = ho;
    } else {
        const int idx = i + (y - 4) * nw4;   // x has 2*nw4 float4s
        float4 v = x[idx];
        uint2 ho, lv;
        split2h(v.x, v.y, ho.x, lv.x);
        split2h(v.z, v.w, ho.y, lv.y);
        xh[idx] = ho;
        xl[idx] = lv;
    }
}

// ============================================================================
// Tensor-core GEMM (NT) body, cp.async multi-stage, ONE sync per chunk.
//   NTERMS=2: C ~= Ah*Bh + Al*Bh ; NTERMS=1: C ~= Ah*Bh (fp32 accum)
// CTA 128x128, K chunk 64. 4 warps (128 thr), warp tile 64x64, 2 CTAs/SM.
// MODE: 0 = fp32 C, 1 = split hi/lo fp16, 2 = rounded fp16
// ============================================================================
#define TKF 64
#define NCHUNK (D_MODEL / TKF)     // 32

template<int NTERMS, int MODE, int NSTAGES>
__device__ __forceinline__
void gemm_body(const __half* __restrict__ Ah,
               const __half* __restrict__ Al,
               const __half* __restrict__ Bh,
               float* __restrict__ C,
               __half* __restrict__ Ch,
               __half* __restrict__ Cl,
               char* smc)
{
    constexpr int NT = NTERMS + 1;               // tiles per stage
    constexpr uint32_t STAGE = (uint32_t)NT * 16384u;
    constexpr uint32_t AL_OFF = 16384u;
    constexpr uint32_t B_OFF  = (uint32_t)(NT - 1) * 16384u;

    const uint32_t sb = smem_u32(smc);
    const int tid  = threadIdx.x;
    const int wid  = tid >> 5;
    const int lane = tid & 31;
    const int bN = blockIdx.x * 128;
    const int bM = blockIdx.y * 128;
    const int wm = (wid & 1) * 64;
    const int wn = (wid >> 1) * 64;

    const int a_row = wm + (lane & 15);
    const int a_kh  = (lane >> 4) * 8;
    const int b_jg  = (lane >> 4);
    const int b_kh  = ((lane >> 3) & 1) * 8;
    const int b_r8  = lane & 7;

    const __half* srcs[3];
    srcs[0] = Ah + (size_t)bM * D_MODEL;
    srcs[1] = (NTERMS == 2) ? (Al + (size_t)bM * D_MODEL)
                            : (Bh + (size_t)bN * D_MODEL);
    srcs[2] = Bh + (size_t)bN * D_MODEL;

    auto prefetch = [&](int c, int stage) {
        const int k0 = c * TKF;
        const uint32_t base = sb + stage * STAGE;
#pragma unroll
        for (int t = 0; t < NT; t++) {
            const __half* s = srcs[t] + k0;
#pragma unroll
            for (int it = 0; it < 8; it++) {
                const int vec = tid + it * 128;
                const int r = vec >> 3, v = vec & 7;
                cpasync16(base + t * 16384 + SW128((uint32_t)(r * 128 + v * 16)),
                          s + (size_t)r * D_MODEL + v * 8);
            }
        }
    };

    float acc[4][8][4] = {};   // warp 64x64: [m-frag][n-frag][4]

    prefetch(0, 0); CP_COMMIT();
    if (NSTAGES == 3) { prefetch(1, 1); CP_COMMIT(); }

    for (int c = 0; c < NCHUNK; c++) {
        // wait for stage c data (in-order group completion)
        if (NSTAGES == 3) {
            if (c + 1 < NCHUNK) { CP_WAIT1(); } else { CP_WAIT0(); }
        } else {
            CP_WAIT0();
        }
        __syncthreads();   // all warps past previous compute; stage (c+NSTAGES-1)%NSTAGES free
        if (c + NSTAGES - 1 < NCHUNK) {
            prefetch(c + NSTAGES - 1, (c + NSTAGES - 1) % NSTAGES);
            CP_COMMIT();
        }

        const uint32_t st = sb + (c % NSTAGES) * STAGE;
#pragma unroll
        for (int ks = 0; ks < 4; ks++) {
            const int k16 = ks * 16;
            uint32_t ahf[4][4], bf[8][2];
#pragma unroll
            for (int i = 0; i < 4; i++)
                ldsm4(ahf[i], st +
                      SW128((uint32_t)((a_row + i * 16) * 128 + (k16 + a_kh) * 2)));
#pragma unroll
            for (int p = 0; p < 4; p++) {
                uint32_t r[4];
                const int jr = wn + (p * 2 + b_jg) * 8 + b_r8;
                ldsm4(r, st + B_OFF + SW128((uint32_t)(jr * 128 + (k16 + b_kh) * 2)));
                bf[p * 2 + 0][0] = r[0]; bf[p * 2 + 0][1] = r[1];
                bf[p * 2 + 1][0] = r[2]; bf[p * 2 + 1][1] = r[3];
            }
#pragma unroll
            for (int i = 0; i < 4; i++)
#pragma unroll
                for (int j = 0; j < 8; j++)
                    mma16816(acc[i][j], ahf[i], bf[j]);
            if (NTERMS == 2) {
                uint32_t alf[4][4];
#pragma unroll
                for (int i = 0; i < 4; i++)
                    ldsm4(alf[i], st + AL_OFF +
                          SW128((uint32_t)((a_row + i * 16) * 128 + (k16 + a_kh) * 2)));
#pragma unroll
                for (int i = 0; i < 4; i++)
#pragma unroll
                    for (int j = 0; j < 8; j++)
                        mma16816(acc[i][j], alf[i], bf[j]);
            }
        }
    }

    const int er = bM + wm + (lane >> 2);
    const int ec = bN + wn + (lane & 3) * 2;
#pragma unroll
    for (int i = 0; i < 4; i++)
#pragma unroll
        for (int j = 0; j < 8; j++) {
            const size_t o0 = (size_t)(er + i * 16) * D_MODEL + ec + j * 8;
            const size_t o1 = (size_t)(er + i * 16 + 8) * D_MODEL + ec + j * 8;
            if (MODE == 0) {
                *(float2*)&C[o0] = make_float2(acc[i][j][0], acc[i][j][1]);
                *(float2*)&C[o1] = make_float2(acc[i][j][2], acc[i][j][3]);
            } else if (MODE == 1) {
                uint32_t h, l;
                split2h(acc[i][j][0], acc[i][j][1], h, l);
                *(uint32_t*)&Ch[o0] = h; *(uint32_t*)&Cl[o0] = l;
                split2h(acc[i][j][2], acc[i][j][3], h, l);
                *(uint32_t*)&Ch[o1] = h; *(uint32_t*)&Cl[o1] = l;
            } else {
                *(uint32_t*)&Ch[o0] = pack2h(acc[i][j][0], acc[i][j][1]);
                *(uint32_t*)&Ch[o1] = pack2h(acc[i][j][2], acc[i][j][3]);
            }
        }
}

#define GEMM_SMEM (3 * 32768)   // 98304 == 2*49152; both variants fit, 2 CTAs/SM

// fused Q/K/V projections: z=0 Q (2-term, split out), z=1 K, z=2 V (1-term)
__global__ __launch_bounds__(128, 2)
void gemm_qkv_kernel(const __half* __restrict__ xh, const __half* __restrict__ xl,
                     const __half* wqh, const __half* wkh, const __half* wvh,
                     __half* Qh, __half* Ql, __half* Kh, __half* Vh)
{
    extern __shared__ char smc[];
    if (blockIdx.z == 0)
        gemm_body<2, 1, 2>(xh, xl, wqh, nullptr, Qh, Ql, smc);
    else if (blockIdx.z == 1)
        gemm_body<1, 2, 3>(xh, nullptr, wkh, nullptr, Kh, nullptr, smc);
    else
        gemm_body<1, 2, 3>(xh, nullptr, wvh, nullptr, Vh, nullptr, smc);
}

// O projection: 1-term input, fp32 output
__global__ __launch_bounds__(128, 2)
void gemm_o_kernel(const __half* __restrict__ Ch, const __half* __restrict__ woh,
                   float* __restrict__ C)
{
    extern __shared__ char smc[];
    gemm_body<1, 0, 3>(Ch, nullptr, woh, C, nullptr, nullptr, smc);
}

// ============================================================================
// Causal flash attention, mma.sync fp16 2-term (Q and P split; K,V rounded),
// base-2 softmax on FMA pipe, cp.async double-buffered K/V.
// CTA = 64 q-rows x full head, K tile 64. 4 warps (128 thr), smem 96KB,
// 2 CTAs/SM (independent CTAs overlap softmax with mma). One sync per tile;
// sum-reduce + l-update deferred past the PV mma issue.
// ============================================================================
#define TQF 64
#define TKN 64
#define FQ_BASE  0
#define FQ_LO    16384
#define FKV_BASE 32768
#define KV_STAGE 32768
#define FLASH_SMEM (FKV_BASE + 2 * KV_STAGE)   // 98304

__global__ __launch_bounds__(128, 2)
void flash_mma_kernel(const __half* __restrict__ Qh, const __half* __restrict__ Ql,
                      const __half* __restrict__ Kh, const __half* __restrict__ Vh,
                      __half* __restrict__ Ch)
{
    extern __shared__ char smf[];
    const uint32_t sb = smem_u32(smf);
    const int tid  = threadIdx.x;
    const int wid  = tid >> 5;
    const int lane = tid & 31;

    const int bh = blockIdx.x;
    const int qt = (int)(gridDim.y - 1) - (int)blockIdx.y;   // heavy-first
    const int b  = bh >> 4;
    const int h  = bh & 15;
    const int q0 = qt * TQF;
    const float C2 = 0.08838834764831845f * 1.4426950408889634f; // scale*log2e

    const size_t qbase  = ((size_t)(b * SEQ + q0)) * D_MODEL + h * HEAD_DIM;
    const size_t kvbase = ((size_t)(b * SEQ)) * D_MODEL + h * HEAD_DIM;

    const int nkt = qt + 1;   // 64-row q tile covers k tiles 0..qt

    auto prefetch_kv = [&](int kt, int stage) {
        const int k0 = kt * TKN;
        const uint32_t st = sb + FKV_BASE + stage * KV_STAGE;
        for (int i = tid; i < TKN * 16; i += 128) {
            const int r = i >> 4, v = i & 15;
            const size_t g = kvbase + (size_t)(k0 + r) * D_MODEL + v * 8;
            const uint32_t so = (uint32_t)((v >> 3) * 8192)
                              + SW128((uint32_t)(r * 128 + (v & 7) * 16));
            cpasync16(st + so,         Kh + g);
            cpasync16(st + 16384 + so, Vh + g);
        }
    };

    // ---- load Q tile (hi+lo), subtiles split at d=64 ----
    for (int i = tid; i < TQF * 16; i += 128) {
        const int r = i >> 4, v = i & 15;
        const uint32_t so = (uint32_t)((v >> 3) * 8192)
                          + SW128((uint32_t)(r * 128 + (v & 7) * 16));
        *(uint4*)(smf + FQ_BASE + so) =
            *(const uint4*)(Qh + qbase + (size_t)r * D_MODEL + v * 8);
        *(uint4*)(smf + FQ_LO + so) =
            *(const uint4*)(Ql + qbase + (size_t)r * D_MODEL + v * 8);
    }
    prefetch_kv(0, 0);
    CP_COMMIT();

    const int wm = wid * 16;
    const int a_row = wm + (lane & 15);
    const int a_kh  = (lane >> 4) * 8;

    float oacc[16][4] = {};
    float m0 = -INFINITY, m1 = -INFINITY, l0 = 0.f, l1 = 0.f;

    for (int kt = 0; kt < nkt; kt++) {
        const int k0 = kt * TKN;
        CP_WAIT0();            // stage kt data (only group outstanding)
        __syncthreads();       // also: all warps done reading the other stage
        if (kt + 1 < nkt) { prefetch_kv(kt + 1, (kt + 1) & 1); CP_COMMIT(); }
        const uint32_t st = sb + FKV_BASE + (kt & 1) * KV_STAGE;

        // ---- S = Q K^T (2-term: Qh*Kh + Ql*Kh) ----
        float sacc[8][4] = {};
#pragma unroll
        for (int s = 0; s < 8; s++) {
            const int sub = s >> 2, kb = (s & 3) * 16;
            const uint32_t qoff = (uint32_t)(sub * 8192) +
                SW128((uint32_t)(a_row * 128 + (kb + a_kh) * 2));
            uint32_t qhf[4], qlf[4], kf[8][2];
            ldsm4(qhf, sb + FQ_BASE + qoff);
            ldsm4(qlf, sb + FQ_LO + qoff);
#pragma unroll
            for (int p = 0; p < 4; p++) {
                uint32_t r[4];
                const int jr = (p * 2 + (lane >> 4)) * 8 + (lane & 7);
                ldsm4(r, st + sub * 8192 +
                      SW128((uint32_t)(jr * 128 + (kb + ((lane >> 3) & 1) * 8) * 2)));
                kf[p * 2 + 0][0] = r[0]; kf[p * 2 + 0][1] = r[1];
                kf[p * 2 + 1][0] = r[2]; kf[p * 2 + 1][1] = r[3];
            }
#pragma unroll
            for (int j = 0; j < 8; j++) mma16816(sacc[j], qhf, kf[j]);
#pragma unroll
            for (int j = 0; j < 8; j++) mma16816(sacc[j], qlf, kf[j]);
        }

        // ---- scale (base-2) + causal mask ----
        const bool needmask = (k0 + TKN - 1) > (q0 + wm);
        const int rl = lane >> 2, cl = (lane & 3) * 2;
#pragma unroll
        for (int j = 0; j < 8; j++)
#pragma unroll
            for (int e = 0; e < 4; e++) {
                float v = sacc[j][e] * C2;
                if (needmask) {
                    const int colg = k0 + 8 * j + cl + (e & 1);
                    const int rowg = q0 + wm + rl + (e >> 1) * 8;
                    if (colg > rowg) v = -INFINITY;
                }
                sacc[j][e] = v;
            }

        // ---- online softmax: max reduce (critical), exp, rescale ----
        float mt0 = -INFINITY, mt1 = -INFINITY;
#pragma unroll
        for (int j = 0; j < 8; j++) {
            mt0 = fmaxf(mt0, fmaxf(sacc[j][0], sacc[j][1]));
            mt1 = fmaxf(mt1, fmaxf(sacc[j][2], sacc[j][3]));
        }
        mt0 = fmaxf(mt0, __shfl_xor_sync(0xFFFFFFFFu, mt0, 1));
        mt0 = fmaxf(mt0, __shfl_xor_sync(0xFFFFFFFFu, mt0, 2));
        mt1 = fmaxf(mt1, __shfl_xor_sync(0xFFFFFFFFu, mt1, 1));
        mt1 = fmaxf(mt1, __shfl_xor_sync(0xFFFFFFFFu, mt1, 2));
        const float mn0 = fmaxf(m0, mt0), mn1 = fmaxf(m1, mt1);
        const float al0 = fexp2(m0 - mn0), al1 = fexp2(m1 - mn1);
        float s0 = 0.f, s1 = 0.f;
#pragma unroll
        for (int j = 0; j < 8; j++) {
            sacc[j][0] = fexp2(sacc[j][0] - mn0); s0 += sacc[j][0];
            sacc[j][1] = fexp2(sacc[j][1] - mn0); s0 += sacc[j][1];
            sacc[j][2] = fexp2(sacc[j][2] - mn1); s1 += sacc[j][2];
            sacc[j][3] = fexp2(sacc[j][3] - mn1); s1 += sacc[j][3];
        }
#pragma unroll
        for (int j = 0; j < 16; j++) {
            oacc[j][0] *= al0; oacc[j][1] *= al0;
            oacc[j][2] *= al1; oacc[j][3] *= al1;
        }

        // ---- O += P V (2-term: Ph*Vh + Pl*Vh), V^T via ldmatrix.trans ----
#pragma unroll
        for (int s2 = 0; s2 < 4; s2++) {
            uint32_t ph[4], pl[4];
            split2h(sacc[2 * s2][0],     sacc[2 * s2][1],     ph[0], pl[0]);
            split2h(sacc[2 * s2][2],     sacc[2 * s2][3],     ph[1], pl[1]);
            split2h(sacc[2 * s2 + 1][0], sacc[2 * s2 + 1][1], ph[2], pl[2]);
            split2h(sacc[2 * s2 + 1][2], sacc[2 * s2 + 1][3], ph[3], pl[3]);
            const int vrow = 16 * s2 + ((lane >> 3) & 1) * 8 + (lane & 7);
#pragma unroll
            for (int p = 0; p < 8; p++) {
                const uint32_t voff = (uint32_t)((p >> 2) * 8192) +
                    SW128((uint32_t)(vrow * 128 + 32 * (p & 3) + (lane >> 4) * 16));
                uint32_t r[4];
                ldsm4t(r, st + 16384 + voff);
                uint32_t b0[2] = { r[0], r[1] }, b1[2] = { r[2], r[3] };
                mma16816(oacc[2 * p],     ph, b0);
                mma16816(oacc[2 * p + 1], ph, b1);
                mma16816(oacc[2 * p],     pl, b0);
                mma16816(oacc[2 * p + 1], pl, b1);
            }
        }

        // ---- deferred: sum reduce + l/m update (off the PV critical path) ----
        s0 += __shfl_xor_sync(0xFFFFFFFFu, s0, 1);
        s0 += __shfl_xor_sync(0xFFFFFFFFu, s0, 2);
        s1 += __shfl_xor_sync(0xFFFFFFFFu, s1, 1);
        s1 += __shfl_xor_sync(0xFFFFFFFFu, s1, 2);
        l0 = l0 * al0 + s0;
        l1 = l1 * al1 + s1;
        m0 = mn0; m1 = mn1;
    }

    // ---- epilogue: normalize, round to fp16, store CTX ----
    const float li0 = 1.f / l0, li1 = 1.f / l1;
    const int r0 = q0 + wm + (lane >> 2);
    const int cbase = h * HEAD_DIM + (lane & 3) * 2;
#pragma unroll
    for (int j = 0; j < 16; j++) {
        const size_t o0 = ((size_t)(b * SEQ + r0)) * D_MODEL + cbase + 8 * j;
        const size_t o1 = ((size_t)(b * SEQ + r0 + 8)) * D_MODEL + cbase + 8 * j;
        *(uint32_t*)&Ch[o0] = pack2h(oacc[j][0] * li0, oacc[j][1] * li0);
        *(uint32_t*)&Ch[o1] = pack2h(oacc[j][2] * li1, oacc[j][3] * li1);
    }
}

// ============================================================================
// launch
// ============================================================================
extern "C" void kernel_launch(void* const* d_in, const int* in_sizes, int n_in,
                              void* d_out, int out_size)
{
    const float* x  = (const float*)d_in[0];
    const float* wq = (const float*)d_in[1];
    const float* wk = (const float*)d_in[2];
    const float* wv = (const float*)d_in[3];
    const float* wo = (const float*)d_in[4];
    float* out = (float*)d_out;

    __half *xh, *xl, *wqh, *wkh, *wvh, *woh;
    __half *Qh, *Ql, *Kh, *Vh, *Ch;
    cudaGetSymbolAddress((void**)&xh, g_xh);
    cudaGetSymbolAddress((void**)&xl, g_xl);
    cudaGetSymbolAddress((void**)&wqh, g_wqh);
    cudaGetSymbolAddress((void**)&wkh, g_wkh);
    cudaGetSymbolAddress((void**)&wvh, g_wvh);
    cudaGetSymbolAddress((void**)&woh, g_woh);
    cudaGetSymbolAddress((void**)&Qh, g_Qh);
    cudaGetSymbolAddress((void**)&Ql, g_Ql);
    cudaGetSymbolAddress((void**)&Kh, g_Kh);
    cudaGetSymbolAddress((void**)&Vh, g_Vh);
    cudaGetSymbolAddress((void**)&Ch, g_Ch);

    cudaFuncSetAttribute(gemm_qkv_kernel,
                         cudaFuncAttributeMaxDynamicSharedMemorySize, GEMM_SMEM);
    cudaFuncSetAttribute(gemm_o_kernel,
                         cudaFuncAttributeMaxDynamicSharedMemorySize, GEMM_SMEM);
    cudaFuncSetAttribute(flash_mma_kernel,
                         cudaFuncAttributeMaxDynamicSharedMemorySize, FLASH_SMEM);

    const int nw4 = D_MODEL * D_MODEL / 4;
    dim3 gg(D_MODEL / 128, M_TOTAL / 128);   // (16, 32)

    prep_kernel<<<dim3((nw4 + 255) / 256, 6), 256>>>(
        (const float4*)x, (const float4*)wq, (const float4*)wk,
        (const float4*)wv, (const float4*)wo,
        (uint2*)xh, (uint2*)xl, (uint2*)wqh, (uint2*)wkh,
        (uint2*)wvh, (uint2*)woh, nw4);

    gemm_qkv_kernel<<<dim3(gg.x, gg.y, 3), 128, GEMM_SMEM>>>(
        xh, xl, wqh, wkh, wvh, Qh, Ql, Kh, Vh);

    flash_mma_kernel<<<dim3(BATCH * NUM_HEADS, SEQ / TQF), 128, FLASH_SMEM>>>(
        Qh, Ql, Kh, Vh, Ch);

    gemm_o_kernel<<<gg, 128, GEMM_SMEM>>>(Ch, woh, out);
}

// round 14
// speedup vs baseline: 1.4318x; 1.4318x over previous
#include <cuda_runtime.h>
#include <cuda_fp16.h>
#include <cstdint>
#include <math.h>

#define D_MODEL   2048
#define NUM_HEADS 16
#define HEAD_DIM  128
#define BATCH     2
#define SEQ       2048
#define M_TOTAL   (BATCH * SEQ)   // 4096

// ---------------- scratch (static device globals: no allocation allowed) ----
__device__ __half g_xh[M_TOTAL * D_MODEL];
__device__ __half g_xl[M_TOTAL * D_MODEL];
__device__ __half g_wqh[D_MODEL * D_MODEL];
__device__ __half g_wkh[D_MODEL * D_MODEL];
__device__ __half g_wvh[D_MODEL * D_MODEL];
__device__ __half g_woh[D_MODEL * D_MODEL];
__device__ __half g_Qh[M_TOTAL * D_MODEL];
__device__ __half g_Ql[M_TOTAL * D_MODEL];
__device__ __half g_Kh[M_TOTAL * D_MODEL];
__device__ __half g_Vh[M_TOTAL * D_MODEL];
__device__ __half g_Ch[M_TOTAL * D_MODEL];

// ============================================================================
// helpers
// ============================================================================
__device__ __forceinline__ uint32_t smem_u32(const void* p) {
    uint32_t a;
    asm("{ .reg .u64 t; cvta.to.shared.u64 t, %1; cvt.u32.u64 %0, t; }"
        : "=r"(a) : "l"(p));
    return a;
}
#define SW128(o) ((o) ^ (((o) >> 3) & 0x70))

__device__ __forceinline__ void ldsm4(uint32_t* r, uint32_t addr) {
    asm volatile("ldmatrix.sync.aligned.m8n8.x4.shared.b16 {%0,%1,%2,%3}, [%4];"
                 : "=r"(r[0]), "=r"(r[1]), "=r"(r[2]), "=r"(r[3]) : "r"(addr));
}
__device__ __forceinline__ void ldsm4t(uint32_t* r, uint32_t addr) {
    asm volatile("ldmatrix.sync.aligned.m8n8.x4.trans.shared.b16 {%0,%1,%2,%3}, [%4];"
                 : "=r"(r[0]), "=r"(r[1]), "=r"(r[2]), "=r"(r[3]) : "r"(addr));
}
__device__ __forceinline__ void mma16816(float* d, const uint32_t* a,
                                         const uint32_t* b) {
    asm volatile(
        "mma.sync.aligned.m16n8k16.row.col.f32.f16.f16.f32 "
        "{%0,%1,%2,%3}, {%4,%5,%6,%7}, {%8,%9}, {%0,%1,%2,%3};"
        : "+f"(d[0]), "+f"(d[1]), "+f"(d[2]), "+f"(d[3])
        : "r"(a[0]), "r"(a[1]), "r"(a[2]), "r"(a[3]), "r"(b[0]), "r"(b[1]));
}
__device__ __forceinline__ void cpasync16(uint32_t dst, const void* src) {
    asm volatile("cp.async.cg.shared.global [%0], [%1], 16;"
                 :: "r"(dst), "l"(src) : "memory");
}
#define CP_COMMIT() asm volatile("cp.async.commit_group;" ::: "memory")
#define CP_WAIT2()  asm volatile("cp.async.wait_group 2;" ::: "memory")
#define CP_WAIT1()  asm volatile("cp.async.wait_group 1;" ::: "memory")
#define CP_WAIT0()  asm volatile("cp.async.wait_group 0;" ::: "memory")

// fp32 pair -> fp16x2 hi + fp16x2 lo (residual)
__device__ __forceinline__ void split2h(float a, float b, uint32_t& hi, uint32_t& lo) {
    __half2 h = __floats2half2_rn(a, b);
    hi = *(uint32_t*)&h;
    float ra = a - __half2float(h.x);
    float rb = b - __half2float(h.y);
    __half2 l = __floats2half2_rn(ra, rb);
    lo = *(uint32_t*)&l;
}
__device__ __forceinline__ uint32_t pack2h(float a, float b) {
    __half2 h = __floats2half2_rn(a, b);
    return *(uint32_t*)&h;
}

// fast 2^y on the FMA/ALU pipes (no MUFU). y <= ~0; -inf -> 0.
__device__ __forceinline__ float fexp2(float y) {
    y = fmaxf(y, -120.f);
    const float t = y + 12582912.f;          // 1.5*2^23: round(y) in mantissa
    const int   i = __float_as_int(t);
    const float f = y - (t - 12582912.f);    // f in [-0.5, 0.5]
    float p = 1.33335581e-3f;
    p = fmaf(p, f, 9.61812910e-3f);
    p = fmaf(p, f, 5.55041087e-2f);
    p = fmaf(p, f, 2.40226507e-1f);
    p = fmaf(p, f, 6.93147181e-1f);
    p = fmaf(p, f, 1.0f);
    return __int_as_float(__float_as_int(p) + (i << 23));
}

// ============================================================================
// prep: weight rounding (y=0..3) + x hi/lo split (y=4,5), one launch
// ============================================================================
__global__ __launch_bounds__(256)
void prep_kernel(const float4* __restrict__ x,
                 const float4* __restrict__ wq, const float4* __restrict__ wk,
                 const float4* __restrict__ wv, const float4* __restrict__ wo,
                 uint2* xh, uint2* xl, uint2* qh, uint2* kh, uint2* vh, uint2* oh,
                 int nw4)
{
    int i = blockIdx.x * blockDim.x + threadIdx.x;
    if (i >= nw4) return;
    const int y = blockIdx.y;
    if (y < 4) {
        const float4* s; uint2* h;
        switch (y) {
            case 0:  s = wq; h = qh; break;
            case 1:  s = wk; h = kh; break;
            case 2:  s = wv; h = vh; break;
            default: s = wo; h = oh; break;
        }
        float4 v = s[i];
        uint2 ho;
        ho.x = pack2h(v.x, v.y);
        ho.y = pack2h(v.z, v.w);
        h[i] = ho;
    } else {
        const int idx = i + (y - 4) * nw4;   // x has 2*nw4 float4s
        float4 v = x[idx];
        uint2 ho, lv;
        split2h(v.x, v.y, ho.x, lv.x);
        split2h(v.z, v.w, ho.y, lv.y);
        xh[idx] = ho;
        xl[idx] = lv;
    }
}

// ============================================================================
// Tensor-core GEMM (NT) body — EXACT R12 structure (two syncs per chunk,
// prefetch issued BEFORE the cp.async wait).
//   NTERMS=2: C ~= Ah*Bh + Al*Bh ; NTERMS=1: C ~= Ah*Bh (fp32 accum)
// CTA 128x128, K chunk 64. 4 warps (128 thr), warp tile 64x64, 2 CTAs/SM.
// MODE: 0 = fp32 C, 1 = split hi/lo fp16, 2 = rounded fp16
// ============================================================================
#define TKF 64
#define NCHUNK (D_MODEL / TKF)     // 32

template<int NTERMS, int MODE, int NSTAGES>
__device__ __forceinline__
void gemm_body(const __half* __restrict__ Ah,
               const __half* __restrict__ Al,
               const __half* __restrict__ Bh,
               float* __restrict__ C,
               __half* __restrict__ Ch,
               __half* __restrict__ Cl,
               char* smc)
{
    constexpr int NT = NTERMS + 1;               // tiles per stage
    constexpr uint32_t STAGE = (uint32_t)NT * 16384u;
    constexpr uint32_t AL_OFF = 16384u;
    constexpr uint32_t B_OFF  = (uint32_t)(NT - 1) * 16384u;

    const uint32_t sb = smem_u32(smc);
    const int tid  = threadIdx.x;
    const int wid  = tid >> 5;
    const int lane = tid & 31;
    const int bN = blockIdx.x * 128;
    const int bM = blockIdx.y * 128;
    const int wm = (wid & 1) * 64;
    const int wn = (wid >> 1) * 64;

    const int a_row = wm + (lane & 15);
    const int a_kh  = (lane >> 4) * 8;
    const int b_jg  = (lane >> 4);
    const int b_kh  = ((lane >> 3) & 1) * 8;
    const int b_r8  = lane & 7;

    const __half* srcs[3];
    srcs[0] = Ah + (size_t)bM * D_MODEL;
    srcs[1] = (NTERMS == 2) ? (Al + (size_t)bM * D_MODEL)
                            : (Bh + (size_t)bN * D_MODEL);
    srcs[2] = Bh + (size_t)bN * D_MODEL;

    auto prefetch = [&](int c, int stage) {
        const int k0 = c * TKF;
        const uint32_t base = sb + stage * STAGE;
#pragma unroll
        for (int t = 0; t < NT; t++) {
            const __half* s = srcs[t] + k0;
#pragma unroll
            for (int it = 0; it < 8; it++) {
                const int vec = tid + it * 128;
                const int r = vec >> 3, v = vec & 7;
                cpasync16(base + t * 16384 + SW128((uint32_t)(r * 128 + v * 16)),
                          s + (size_t)r * D_MODEL + v * 8);
            }
        }
    };

    float acc[4][8][4] = {};   // warp 64x64: [m-frag][n-frag][4]

    prefetch(0, 0); CP_COMMIT();
    if (NSTAGES == 3) { prefetch(1, 1); CP_COMMIT(); }

    for (int c = 0; c < NCHUNK; c++) {
        if (NSTAGES == 3) {
            if (c + 2 < NCHUNK)      { prefetch(c + 2, (c + 2) % 3); CP_COMMIT(); CP_WAIT2(); }
            else if (c + 1 < NCHUNK) { CP_WAIT1(); }
            else                     { CP_WAIT0(); }
        } else {
            if (c + 1 < NCHUNK) { prefetch(c + 1, (c + 1) & 1); CP_COMMIT(); CP_WAIT1(); }
            else                { CP_WAIT0(); }
        }
        __syncthreads();

        const uint32_t st = sb + (c % NSTAGES) * STAGE;
#pragma unroll
        for (int ks = 0; ks < 4; ks++) {
            const int k16 = ks * 16;
            uint32_t ahf[4][4], bf[8][2];
#pragma unroll
            for (int i = 0; i < 4; i++)
                ldsm4(ahf[i], st +
                      SW128((uint32_t)((a_row + i * 16) * 128 + (k16 + a_kh) * 2)));
#pragma unroll
            for (int p = 0; p < 4; p++) {
                uint32_t r[4];
                const int jr = wn + (p * 2 + b_jg) * 8 + b_r8;
                ldsm4(r, st + B_OFF + SW128((uint32_t)(jr * 128 + (k16 + b_kh) * 2)));
                bf[p * 2 + 0][0] = r[0]; bf[p * 2 + 0][1] = r[1];
                bf[p * 2 + 1][0] = r[2]; bf[p * 2 + 1][1] = r[3];
            }
#pragma unroll
            for (int i = 0; i < 4; i++)
#pragma unroll
                for (int j = 0; j < 8; j++)
                    mma16816(acc[i][j], ahf[i], bf[j]);
            if (NTERMS == 2) {
                uint32_t alf[4][4];
#pragma unroll
                for (int i = 0; i < 4; i++)
                    ldsm4(alf[i], st + AL_OFF +
                          SW128((uint32_t)((a_row + i * 16) * 128 + (k16 + a_kh) * 2)));
#pragma unroll
                for (int i = 0; i < 4; i++)
#pragma unroll
                    for (int j = 0; j < 8; j++)
                        mma16816(acc[i][j], alf[i], bf[j]);
            }
        }
        __syncthreads();
    }

    const int er = bM + wm + (lane >> 2);
    const int ec = bN + wn + (lane & 3) * 2;
#pragma unroll
    for (int i = 0; i < 4; i++)
#pragma unroll
        for (int j = 0; j < 8; j++) {
            const size_t o0 = (size_t)(er + i * 16) * D_MODEL + ec + j * 8;
            const size_t o1 = (size_t)(er + i * 16 + 8) * D_MODEL + ec + j * 8;
            if (MODE == 0) {
                *(float2*)&C[o0] = make_float2(acc[i][j][0], acc[i][j][1]);
                *(float2*)&C[o1] = make_float2(acc[i][j][2], acc[i][j][3]);
            } else if (MODE == 1) {
                uint32_t h, l;
                split2h(acc[i][j][0], acc[i][j][1], h, l);
                *(uint32_t*)&Ch[o0] = h; *(uint32_t*)&Cl[o0] = l;
                split2h(acc[i][j][2], acc[i][j][3], h, l);
                *(uint32_t*)&Ch[o1] = h; *(uint32_t*)&Cl[o1] = l;
            } else {
                *(uint32_t*)&Ch[o0] = pack2h(acc[i][j][0], acc[i][j][1]);
                *(uint32_t*)&Ch[o1] = pack2h(acc[i][j][2], acc[i][j][3]);
            }
        }
}

#define GEMM_SMEM_2T (2 * 49152)   // 98304 (2-stage, 2 CTAs/SM)
#define GEMM_SMEM_1T (3 * 32768)   // 98304 (3-stage, 2 CTAs/SM)

// Q projection: 2-term input, split hi/lo output
__global__ __launch_bounds__(128, 2)
void gemm_q_kernel(const __half* __restrict__ xh, const __half* __restrict__ xl,
                   const __half* __restrict__ wqh,
                   __half* __restrict__ Qh, __half* __restrict__ Ql)
{
    extern __shared__ char smc[];
    gemm_body<2, 1, 2>(xh, xl, wqh, nullptr, Qh, Ql, smc);
}

// K/V projections: 1-term input, rounded output; z selects K or V
__global__ __launch_bounds__(128, 2)
void gemm_kv_kernel(const __half* __restrict__ xh,
                    const __half* __restrict__ wkh, const __half* __restrict__ wvh,
                    __half* __restrict__ Kh, __half* __restrict__ Vh)
{
    extern __shared__ char smc[];
    if (blockIdx.z == 0)
        gemm_body<1, 2, 3>(xh, nullptr, wkh, nullptr, Kh, nullptr, smc);
    else
        gemm_body<1, 2, 3>(xh, nullptr, wvh, nullptr, Vh, nullptr, smc);
}

// O projection: 1-term input, fp32 output
__global__ __launch_bounds__(128, 2)
void gemm_o_kernel(const __half* __restrict__ Ch, const __half* __restrict__ woh,
                   float* __restrict__ C)
{
    extern __shared__ char smc[];
    gemm_body<1, 0, 3>(Ch, nullptr, woh, C, nullptr, nullptr, smc);
}

// ============================================================================
// Causal flash attention (R13 version): fp16 2-term, base-2 softmax,
// cp.async double-buffered K/V. CTA = 64 q-rows, 4 warps, smem 96KB,
// 2 CTAs/SM; deferred sum-reduce/l-update past the PV mma issue.
// ============================================================================
#define TQF 64
#define TKN 64
#define FQ_BASE  0
#define FQ_LO    16384
#define FKV_BASE 32768
#define KV_STAGE 32768
#define FLASH_SMEM (FKV_BASE + 2 * KV_STAGE)   // 98304

__global__ __launch_bounds__(128, 2)
void flash_mma_kernel(const __half* __restrict__ Qh, const __half* __restrict__ Ql,
                      const __half* __restrict__ Kh, const __half* __restrict__ Vh,
                      __half* __restrict__ Ch)
{
    extern __shared__ char smf[];
    const uint32_t sb = smem_u32(smf);
    const int tid  = threadIdx.x;
    const int wid  = tid >> 5;
    const int lane = tid & 31;

    const int bh = blockIdx.x;
    const int qt = (int)(gridDim.y - 1) - (int)blockIdx.y;   // heavy-first
    const int b  = bh >> 4;
    const int h  = bh & 15;
    const int q0 = qt * TQF;
    const float C2 = 0.08838834764831845f * 1.4426950408889634f; // scale*log2e

    const size_t qbase  = ((size_t)(b * SEQ + q0)) * D_MODEL + h * HEAD_DIM;
    const size_t kvbase = ((size_t)(b * SEQ)) * D_MODEL + h * HEAD_DIM;

    const int nkt = qt + 1;   // 64-row q tile covers k tiles 0..qt

    auto prefetch_kv = [&](int kt, int stage) {
        const int k0 = kt * TKN;
        const uint32_t st = sb + FKV_BASE + stage * KV_STAGE;
        for (int i = tid; i < TKN * 16; i += 128) {
            const int r = i >> 4, v = i & 15;
            const size_t g = kvbase + (size_t)(k0 + r) * D_MODEL + v * 8;
            const uint32_t so = (uint32_t)((v >> 3) * 8192)
                              + SW128((uint32_t)(r * 128 + (v & 7) * 16));
            cpasync16(st + so,         Kh + g);
            cpasync16(st + 16384 + so, Vh + g);
        }
    };

    // ---- load Q tile (hi+lo), subtiles split at d=64 ----
    for (int i = tid; i < TQF * 16; i += 128) {
        const int r = i >> 4, v = i & 15;
        const uint32_t so = (uint32_t)((v >> 3) * 8192)
                          + SW128((uint32_t)(r * 128 + (v & 7) * 16));
        *(uint4*)(smf + FQ_BASE + so) =
            *(const uint4*)(Qh + qbase + (size_t)r * D_MODEL + v * 8);
        *(uint4*)(smf + FQ_LO + so) =
            *(const uint4*)(Ql + qbase + (size_t)r * D_MODEL + v * 8);
    }
    prefetch_kv(0, 0);
    CP_COMMIT();

    const int wm = wid * 16;
    const int a_row = wm + (lane & 15);
    const int a_kh  = (lane >> 4) * 8;

    float oacc[16][4] = {};
    float m0 = -INFINITY, m1 = -INFINITY, l0 = 0.f, l1 = 0.f;

    for (int kt = 0; kt < nkt; kt++) {
        const int k0 = kt * TKN;
        CP_WAIT0();            // stage kt data (only group outstanding)
        __syncthreads();       // also: all warps done reading the other stage
        if (kt + 1 < nkt) { prefetch_kv(kt + 1, (kt + 1) & 1); CP_COMMIT(); }
        const uint32_t st = sb + FKV_BASE + (kt & 1) * KV_STAGE;

        // ---- S = Q K^T (2-term: Qh*Kh + Ql*Kh) ----
        float sacc[8][4] = {};
#pragma unroll
        for (int s = 0; s < 8; s++) {
            const int sub = s >> 2, kb = (s & 3) * 16;
            const uint32_t qoff = (uint32_t)(sub * 8192) +
                SW128((uint32_t)(a_row * 128 + (kb + a_kh) * 2));
            uint32_t qhf[4], qlf[4], kf[8][2];
            ldsm4(qhf, sb + FQ_BASE + qoff);
            ldsm4(qlf, sb + FQ_LO + qoff);
#pragma unroll
            for (int p = 0; p < 4; p++) {
                uint32_t r[4];
                const int jr = (p * 2 + (lane >> 4)) * 8 + (lane & 7);
                ldsm4(r, st + sub * 8192 +
                      SW128((uint32_t)(jr * 128 + (kb + ((lane >> 3) & 1) * 8) * 2)));
                kf[p * 2 + 0][0] = r[0]; kf[p * 2 + 0][1] = r[1];
                kf[p * 2 + 1][0] = r[2]; kf[p * 2 + 1][1] = r[3];
            }
#pragma unroll
            for (int j = 0; j < 8; j++) mma16816(sacc[j], qhf, kf[j]);
#pragma unroll
            for (int j = 0; j < 8; j++) mma16816(sacc[j], qlf, kf[j]);
        }

        // ---- scale (base-2) + causal mask ----
        const bool needmask = (k0 + TKN - 1) > (q0 + wm);
        const int rl = lane >> 2, cl = (lane & 3) * 2;
#pragma unroll
        for (int j = 0; j < 8; j++)
#pragma unroll
            for (int e = 0; e < 4; e++) {
                float v = sacc[j][e] * C2;
                if (needmask) {
                    const int colg = k0 + 8 * j + cl + (e & 1);
                    const int rowg = q0 + wm + rl + (e >> 1) * 8;
                    if (colg > rowg) v = -INFINITY;
                }
                sacc[j][e] = v;
            }

        // ---- online softmax: max reduce (critical), exp, rescale ----
        float mt0 = -INFINITY, mt1 = -INFINITY;
#pragma unroll
        for (int j = 0; j < 8; j++) {
            mt0 = fmaxf(mt0, fmaxf(sacc[j][0], sacc[j][1]));
            mt1 = fmaxf(mt1, fmaxf(sacc[j][2], sacc[j][3]));
        }
        mt0 = fmaxf(mt0, __shfl_xor_sync(0xFFFFFFFFu, mt0, 1));
        mt0 = fmaxf(mt0, __shfl_xor_sync(0xFFFFFFFFu, mt0, 2));
        mt1 = fmaxf(mt1, __shfl_xor_sync(0xFFFFFFFFu, mt1, 1));
        mt1 = fmaxf(mt1, __shfl_xor_sync(0xFFFFFFFFu, mt1, 2));
        const float mn0 = fmaxf(m0, mt0), mn1 = fmaxf(m1, mt1);
        const float al0 = fexp2(m0 - mn0), al1 = fexp2(m1 - mn1);
        float s0 = 0.f, s1 = 0.f;
#pragma unroll
        for (int j = 0; j < 8; j++) {
            sacc[j][0] = fexp2(sacc[j][0] - mn0); s0 += sacc[j][0];
            sacc[j][1] = fexp2(sacc[j][1] - mn0); s0 += sacc[j][1];
            sacc[j][2] = fexp2(sacc[j][2] - mn1); s1 += sacc[j][2];
            sacc[j][3] = fexp2(sacc[j][3] - mn1); s1 += sacc[j][3];
        }
#pragma unroll
        for (int j = 0; j < 16; j++) {
            oacc[j][0] *= al0; oacc[j][1] *= al0;
            oacc[j][2] *= al1; oacc[j][3] *= al1;
        }

        // ---- O += P V (2-term: Ph*Vh + Pl*Vh), V^T via ldmatrix.trans ----
#pragma unroll
        for (int s2 = 0; s2 < 4; s2++) {
            uint32_t ph[4], pl[4];
            split2h(sacc[2 * s2][0],     sacc[2 * s2][1],     ph[0], pl[0]);
            split2h(sacc[2 * s2][2],     sacc[2 * s2][3],     ph[1], pl[1]);
            split2h(sacc[2 * s2 + 1][0], sacc[2 * s2 + 1][1], ph[2], pl[2]);
            split2h(sacc[2 * s2 + 1][2], sacc[2 * s2 + 1][3], ph[3], pl[3]);
            const int vrow = 16 * s2 + ((lane >> 3) & 1) * 8 + (lane & 7);
#pragma unroll
            for (int p = 0; p < 8; p++) {
                const uint32_t voff = (uint32_t)((p >> 2) * 8192) +
                    SW128((uint32_t)(vrow * 128 + 32 * (p & 3) + (lane >> 4) * 16));
                uint32_t r[4];
                ldsm4t(r, st + 16384 + voff);
                uint32_t b0[2] = { r[0], r[1] }, b1[2] = { r[2], r[3] };
                mma16816(oacc[2 * p],     ph, b0);
                mma16816(oacc[2 * p + 1], ph, b1);
                mma16816(oacc[2 * p],     pl, b0);
                mma16816(oacc[2 * p + 1], pl, b1);
            }
        }

        // ---- deferred: sum reduce + l/m update (off the PV critical path) ----
        s0 += __shfl_xor_sync(0xFFFFFFFFu, s0, 1);
        s0 += __shfl_xor_sync(0xFFFFFFFFu, s0, 2);
        s1 += __shfl_xor_sync(0xFFFFFFFFu, s1, 1);
        s1 += __shfl_xor_sync(0xFFFFFFFFu, s1, 2);
        l0 = l0 * al0 + s0;
        l1 = l1 * al1 + s1;
        m0 = mn0; m1 = mn1;
    }

    // ---- epilogue: normalize, round to fp16, store CTX ----
    const float li0 = 1.f / l0, li1 = 1.f / l1;
    const int r0 = q0 + wm + (lane >> 2);
    const int cbase = h * HEAD_DIM + (lane & 3) * 2;
#pragma unroll
    for (int j = 0; j < 16; j++) {
        const size_t o0 = ((size_t)(b * SEQ + r0)) * D_MODEL + cbase + 8 * j;
        const size_t o1 = ((size_t)(b * SEQ + r0 + 8)) * D_MODEL + cbase + 8 * j;
        *(uint32_t*)&Ch[o0] = pack2h(oacc[j][0] * li0, oacc[j][1] * li0);
        *(uint32_t*)&Ch[o1] = pack2h(oacc[j][2] * li1, oacc[j][3] * li1);
    }
}

// ============================================================================
// launch
// ============================================================================
extern "C" void kernel_launch(void* const* d_in, const int* in_sizes, int n_in,
                              void* d_out, int out_size)
{
    const float* x  = (const float*)d_in[0];
    const float* wq = (const float*)d_in[1];
    const float* wk = (const float*)d_in[2];
    const float* wv = (const float*)d_in[3];
    const float* wo = (const float*)d_in[4];
    float* out = (float*)d_out;

    __half *xh, *xl, *wqh, *wkh, *wvh, *woh;
    __half *Qh, *Ql, *Kh, *Vh, *Ch;
    cudaGetSymbolAddress((void**)&xh, g_xh);
    cudaGetSymbolAddress((void**)&xl, g_xl);
    cudaGetSymbolAddress((void**)&wqh, g_wqh);
    cudaGetSymbolAddress((void**)&wkh, g_wkh);
    cudaGetSymbolAddress((void**)&wvh, g_wvh);
    cudaGetSymbolAddress((void**)&woh, g_woh);
    cudaGetSymbolAddress((void**)&Qh, g_Qh);
    cudaGetSymbolAddress((void**)&Ql, g_Ql);
    cudaGetSymbolAddress((void**)&Kh, g_Kh);
    cudaGetSymbolAddress((void**)&Vh, g_Vh);
    cudaGetSymbolAddress((void**)&Ch, g_Ch);

    cudaFuncSetAttribute(gemm_q_kernel,
                         cudaFuncAttributeMaxDynamicSharedMemorySize, GEMM_SMEM_2T);
    cudaFuncSetAttribute(gemm_kv_kernel,
                         cudaFuncAttributeMaxDynamicSharedMemorySize, GEMM_SMEM_1T);
    cudaFuncSetAttribute(gemm_o_kernel,
                         cudaFuncAttributeMaxDynamicSharedMemorySize, GEMM_SMEM_1T);
    cudaFuncSetAttribute(flash_mma_kernel,
                         cudaFuncAttributeMaxDynamicSharedMemorySize, FLASH_SMEM);

    const int nw4 = D_MODEL * D_MODEL / 4;
    dim3 gg(D_MODEL / 128, M_TOTAL / 128);   // (16, 32)

    prep_kernel<<<dim3((nw4 + 255) / 256, 6), 256>>>(
        (const float4*)x, (const float4*)wq, (const float4*)wk,
        (const float4*)wv, (const float4*)wo,
        (uint2*)xh, (uint2*)xl, (uint2*)wqh, (uint2*)wkh,
        (uint2*)wvh, (uint2*)woh, nw4);

    gemm_q_kernel<<<gg, 128, GEMM_SMEM_2T>>>(xh, xl, wqh, Qh, Ql);
    gemm_kv_kernel<<<dim3(gg.x, gg.y, 2), 128, GEMM_SMEM_1T>>>(xh, wkh, wvh, Kh, Vh);

    flash_mma_kernel<<<dim3(BATCH * NUM_HEADS, SEQ / TQF), 128, FLASH_SMEM>>>(
        Qh, Ql, Kh, Vh, Ch);

    gemm_o_kernel<<<gg, 128, GEMM_SMEM_1T>>>(Ch, woh, out);
}

// round 15
// speedup vs baseline: 1.5368x; 1.0734x over previous
#include <cuda_runtime.h>
#include <cuda_fp16.h>
#include <cstdint>
#include <math.h>

#define D_MODEL   2048
#define NUM_HEADS 16
#define HEAD_DIM  128
#define BATCH     2
#define SEQ       2048
#define M_TOTAL   (BATCH * SEQ)   // 4096

// ---------------- scratch (static device globals: no allocation allowed) ----
__device__ __half g_xh[M_TOTAL * D_MODEL];
__device__ __half g_xl[M_TOTAL * D_MODEL];
__device__ __half g_wqh[D_MODEL * D_MODEL];
__device__ __half g_wkh[D_MODEL * D_MODEL];
__device__ __half g_wvh[D_MODEL * D_MODEL];
__device__ __half g_woh[D_MODEL * D_MODEL];
__device__ __half g_Qh[M_TOTAL * D_MODEL];
__device__ __half g_Ql[M_TOTAL * D_MODEL];
__device__ __half g_Kh[M_TOTAL * D_MODEL];
__device__ __half g_Vh[M_TOTAL * D_MODEL];
__device__ __half g_Ch[M_TOTAL * D_MODEL];

// ============================================================================
// helpers
// ============================================================================
__device__ __forceinline__ uint32_t smem_u32(const void* p) {
    uint32_t a;
    asm("{ .reg .u64 t; cvta.to.shared.u64 t, %1; cvt.u32.u64 %0, t; }"
        : "=r"(a) : "l"(p));
    return a;
}
#define SW128(o) ((o) ^ (((o) >> 3) & 0x70))

__device__ __forceinline__ void ldsm4(uint32_t* r, uint32_t addr) {
    asm volatile("ldmatrix.sync.aligned.m8n8.x4.shared.b16 {%0,%1,%2,%3}, [%4];"
                 : "=r"(r[0]), "=r"(r[1]), "=r"(r[2]), "=r"(r[3]) : "r"(addr));
}
__device__ __forceinline__ void ldsm4t(uint32_t* r, uint32_t addr) {
    asm volatile("ldmatrix.sync.aligned.m8n8.x4.trans.shared.b16 {%0,%1,%2,%3}, [%4];"
                 : "=r"(r[0]), "=r"(r[1]), "=r"(r[2]), "=r"(r[3]) : "r"(addr));
}
__device__ __forceinline__ void mma16816(float* d, const uint32_t* a,
                                         const uint32_t* b) {
    asm volatile(
        "mma.sync.aligned.m16n8k16.row.col.f32.f16.f16.f32 "
        "{%0,%1,%2,%3}, {%4,%5,%6,%7}, {%8,%9}, {%0,%1,%2,%3};"
        : "+f"(d[0]), "+f"(d[1]), "+f"(d[2]), "+f"(d[3])
        : "r"(a[0]), "r"(a[1]), "r"(a[2]), "r"(a[3]), "r"(b[0]), "r"(b[1]));
}
__device__ __forceinline__ void cpasync16(uint32_t dst, const void* src) {
    asm volatile("cp.async.cg.shared.global [%0], [%1], 16;"
                 :: "r"(dst), "l"(src) : "memory");
}
#define CP_COMMIT() asm volatile("cp.async.commit_group;" ::: "memory")
#define CP_WAIT2()  asm volatile("cp.async.wait_group 2;" ::: "memory")
#define CP_WAIT1()  asm volatile("cp.async.wait_group 1;" ::: "memory")
#define CP_WAIT0()  asm volatile("cp.async.wait_group 0;" ::: "memory")

// fp32 pair -> fp16x2 hi + fp16x2 lo (residual)
__device__ __forceinline__ void split2h(float a, float b, uint32_t& hi, uint32_t& lo) {
    __half2 h = __floats2half2_rn(a, b);
    hi = *(uint32_t*)&h;
    float ra = a - __half2float(h.x);
    float rb = b - __half2float(h.y);
    __half2 l = __floats2half2_rn(ra, rb);
    lo = *(uint32_t*)&l;
}
__device__ __forceinline__ uint32_t pack2h(float a, float b) {
    __half2 h = __floats2half2_rn(a, b);
    return *(uint32_t*)&h;
}

// fast 2^y on the FMA/ALU pipes (no MUFU). y <= ~0; -inf -> 0.
__device__ __forceinline__ float fexp2(float y) {
    y = fmaxf(y, -120.f);
    const float t = y + 12582912.f;          // 1.5*2^23: round(y) in mantissa
    const int   i = __float_as_int(t);
    const float f = y - (t - 12582912.f);    // f in [-0.5, 0.5]
    float p = 1.33335581e-3f;
    p = fmaf(p, f, 9.61812910e-3f);
    p = fmaf(p, f, 5.55041087e-2f);
    p = fmaf(p, f, 2.40226507e-1f);
    p = fmaf(p, f, 6.93147181e-1f);
    p = fmaf(p, f, 1.0f);
    return __int_as_float(__float_as_int(p) + (i << 23));
}

// ============================================================================
// prep: weight rounding (y=0..3) + x hi/lo split (y=4,5), one launch
// ============================================================================
__global__ __launch_bounds__(256)
void prep_kernel(const float4* __restrict__ x,
                 const float4* __restrict__ wq, const float4* __restrict__ wk,
                 const float4* __restrict__ wv, const float4* __restrict__ wo,
                 uint2* xh, uint2* xl, uint2* qh, uint2* kh, uint2* vh, uint2* oh,
                 int nw4)
{
    int i = blockIdx.x * blockDim.x + threadIdx.x;
    if (i >= nw4) return;
    const int y = blockIdx.y;
    if (y < 4) {
        const float4* s; uint2* h;
        switch (y) {
            case 0:  s = wq; h = qh; break;
            case 1:  s = wk; h = kh; break;
            case 2:  s = wv; h = vh; break;
            default: s = wo; h = oh; break;
        }
        float4 v = s[i];
        uint2 ho;
        ho.x = pack2h(v.x, v.y);
        ho.y = pack2h(v.z, v.w);
        h[i] = ho;
    } else {
        const int idx = i + (y - 4) * nw4;   // x has 2*nw4 float4s
        float4 v = x[idx];
        uint2 ho, lv;
        split2h(v.x, v.y, ho.x, lv.x);
        split2h(v.z, v.w, ho.y, lv.y);
        xh[idx] = ho;
        xl[idx] = lv;
    }
}

// ============================================================================
// Tensor-core GEMM (NT) body — R12/R14 proven structure (two syncs per chunk,
// prefetch issued BEFORE the cp.async wait). DO NOT restructure (R13 lesson).
//   NTERMS=2: C ~= Ah*Bh + Al*Bh ; NTERMS=1: C ~= Ah*Bh (fp32 accum)
// CTA 128x128, K chunk 64. 4 warps (128 thr), warp tile 64x64, 2 CTAs/SM.
// MODE: 0 = fp32 C, 1 = split hi/lo fp16, 2 = rounded fp16
// ============================================================================
#define TKF 64
#define NCHUNK (D_MODEL / TKF)     // 32

template<int NTERMS, int MODE, int NSTAGES>
__device__ __forceinline__
void gemm_body(const __half* __restrict__ Ah,
               const __half* __restrict__ Al,
               const __half* __restrict__ Bh,
               float* __restrict__ C,
               __half* __restrict__ Ch,
               __half* __restrict__ Cl,
               char* smc)
{
    constexpr int NT = NTERMS + 1;               // tiles per stage
    constexpr uint32_t STAGE = (uint32_t)NT * 16384u;
    constexpr uint32_t AL_OFF = 16384u;
    constexpr uint32_t B_OFF  = (uint32_t)(NT - 1) * 16384u;

    const uint32_t sb = smem_u32(smc);
    const int tid  = threadIdx.x;
    const int wid  = tid >> 5;
    const int lane = tid & 31;
    const int bN = blockIdx.x * 128;
    const int bM = blockIdx.y * 128;
    const int wm = (wid & 1) * 64;
    const int wn = (wid >> 1) * 64;

    const int a_row = wm + (lane & 15);
    const int a_kh  = (lane >> 4) * 8;
    const int b_jg  = (lane >> 4);
    const int b_kh  = ((lane >> 3) & 1) * 8;
    const int b_r8  = lane & 7;

    const __half* srcs[3];
    srcs[0] = Ah + (size_t)bM * D_MODEL;
    srcs[1] = (NTERMS == 2) ? (Al + (size_t)bM * D_MODEL)
                            : (Bh + (size_t)bN * D_MODEL);
    srcs[2] = Bh + (size_t)bN * D_MODEL;

    auto prefetch = [&](int c, int stage) {
        const int k0 = c * TKF;
        const uint32_t base = sb + stage * STAGE;
#pragma unroll
        for (int t = 0; t < NT; t++) {
            const __half* s = srcs[t] + k0;
#pragma unroll
            for (int it = 0; it < 8; it++) {
                const int vec = tid + it * 128;
                const int r = vec >> 3, v = vec & 7;
                cpasync16(base + t * 16384 + SW128((uint32_t)(r * 128 + v * 16)),
                          s + (size_t)r * D_MODEL + v * 8);
            }
        }
    };

    float acc[4][8][4] = {};   // warp 64x64: [m-frag][n-frag][4]

    prefetch(0, 0); CP_COMMIT();
    if (NSTAGES == 3) { prefetch(1, 1); CP_COMMIT(); }

    for (int c = 0; c < NCHUNK; c++) {
        if (NSTAGES == 3) {
            if (c + 2 < NCHUNK)      { prefetch(c + 2, (c + 2) % 3); CP_COMMIT(); CP_WAIT2(); }
            else if (c + 1 < NCHUNK) { CP_WAIT1(); }
            else                     { CP_WAIT0(); }
        } else {
            if (c + 1 < NCHUNK) { prefetch(c + 1, (c + 1) & 1); CP_COMMIT(); CP_WAIT1(); }
            else                { CP_WAIT0(); }
        }
        __syncthreads();

        const uint32_t st = sb + (c % NSTAGES) * STAGE;
#pragma unroll
        for (int ks = 0; ks < 4; ks++) {
            const int k16 = ks * 16;
            uint32_t ahf[4][4], bf[8][2];
#pragma unroll
            for (int i = 0; i < 4; i++)
                ldsm4(ahf[i], st +
                      SW128((uint32_t)((a_row + i * 16) * 128 + (k16 + a_kh) * 2)));
#pragma unroll
            for (int p = 0; p < 4; p++) {
                uint32_t r[4];
                const int jr = wn + (p * 2 + b_jg) * 8 + b_r8;
                ldsm4(r, st + B_OFF + SW128((uint32_t)(jr * 128 + (k16 + b_kh) * 2)));
                bf[p * 2 + 0][0] = r[0]; bf[p * 2 + 0][1] = r[1];
                bf[p * 2 + 1][0] = r[2]; bf[p * 2 + 1][1] = r[3];
            }
#pragma unroll
            for (int i = 0; i < 4; i++)
#pragma unroll
                for (int j = 0; j < 8; j++)
                    mma16816(acc[i][j], ahf[i], bf[j]);
            if (NTERMS == 2) {
                uint32_t alf[4][4];
#pragma unroll
                for (int i = 0; i < 4; i++)
                    ldsm4(alf[i], st + AL_OFF +
                          SW128((uint32_t)((a_row + i * 16) * 128 + (k16 + a_kh) * 2)));
#pragma unroll
                for (int i = 0; i < 4; i++)
#pragma unroll
                    for (int j = 0; j < 8; j++)
                        mma16816(acc[i][j], alf[i], bf[j]);
            }
        }
        __syncthreads();
    }

    const int er = bM + wm + (lane >> 2);
    const int ec = bN + wn + (lane & 3) * 2;
#pragma unroll
    for (int i = 0; i < 4; i++)
#pragma unroll
        for (int j = 0; j < 8; j++) {
            const size_t o0 = (size_t)(er + i * 16) * D_MODEL + ec + j * 8;
            const size_t o1 = (size_t)(er + i * 16 + 8) * D_MODEL + ec + j * 8;
            if (MODE == 0) {
                *(float2*)&C[o0] = make_float2(acc[i][j][0], acc[i][j][1]);
                *(float2*)&C[o1] = make_float2(acc[i][j][2], acc[i][j][3]);
            } else if (MODE == 1) {
                uint32_t h, l;
                split2h(acc[i][j][0], acc[i][j][1], h, l);
                *(uint32_t*)&Ch[o0] = h; *(uint32_t*)&Cl[o0] = l;
                split2h(acc[i][j][2], acc[i][j][3], h, l);
                *(uint32_t*)&Ch[o1] = h; *(uint32_t*)&Cl[o1] = l;
            } else {
                *(uint32_t*)&Ch[o0] = pack2h(acc[i][j][0], acc[i][j][1]);
                *(uint32_t*)&Ch[o1] = pack2h(acc[i][j][2], acc[i][j][3]);
            }
        }
}

#define GEMM_SMEM 98304   // 2-term 2-stage = 2*49152; 1-term 3-stage = 3*32768

// fused Q/K/V projections in ONE launch (z=0 Q 2-term, z=1 K, z=2 V 1-term):
// K/V CTAs fill the gemm_q tail wave; bodies are byte-identical to R14.
__global__ __launch_bounds__(128, 2)
void gemm_qkv_kernel(const __half* __restrict__ xh, const __half* __restrict__ xl,
                     const __half* __restrict__ wqh,
                     const __half* __restrict__ wkh,
                     const __half* __restrict__ wvh,
                     __half* __restrict__ Qh, __half* __restrict__ Ql,
                     __half* __restrict__ Kh, __half* __restrict__ Vh)
{
    extern __shared__ char smc[];
    if (blockIdx.z == 0)
        gemm_body<2, 1, 2>(xh, xl, wqh, nullptr, Qh, Ql, smc);
    else if (blockIdx.z == 1)
        gemm_body<1, 2, 3>(xh, nullptr, wkh, nullptr, Kh, nullptr, smc);
    else
        gemm_body<1, 2, 3>(xh, nullptr, wvh, nullptr, Vh, nullptr, smc);
}

// O projection: 1-term input, fp32 output
__global__ __launch_bounds__(128, 2)
void gemm_o_kernel(const __half* __restrict__ Ch, const __half* __restrict__ woh,
                   float* __restrict__ C)
{
    extern __shared__ char smc[];
    gemm_body<1, 0, 3>(Ch, nullptr, woh, C, nullptr, nullptr, smc);
}

// ============================================================================
// Causal flash attention (R14 version, untouched): fp16 2-term, base-2
// softmax, cp.async double-buffered K/V. CTA = 64 q-rows, 4 warps, 96KB smem,
// 2 CTAs/SM; deferred sum-reduce/l-update past the PV mma issue.
// ============================================================================
#define TQF 64
#define TKN 64
#define FQ_BASE  0
#define FQ_LO    16384
#define FKV_BASE 32768
#define KV_STAGE 32768
#define FLASH_SMEM (FKV_BASE + 2 * KV_STAGE)   // 98304

__global__ __launch_bounds__(128, 2)
void flash_mma_kernel(const __half* __restrict__ Qh, const __half* __restrict__ Ql,
                      const __half* __restrict__ Kh, const __half* __restrict__ Vh,
                      __half* __restrict__ Ch)
{
    extern __shared__ char smf[];
    const uint32_t sb = smem_u32(smf);
    const int tid  = threadIdx.x;
    const int wid  = tid >> 5;
    const int lane = tid & 31;

    const int bh = blockIdx.x;
    const int qt = (int)(gridDim.y - 1) - (int)blockIdx.y;   // heavy-first
    const int b  = bh >> 4;
    const int h  = bh & 15;
    const int q0 = qt * TQF;
    const float C2 = 0.08838834764831845f * 1.4426950408889634f; // scale*log2e

    const size_t qbase  = ((size_t)(b * SEQ + q0)) * D_MODEL + h * HEAD_DIM;
    const size_t kvbase = ((size_t)(b * SEQ)) * D_MODEL + h * HEAD_DIM;

    const int nkt = qt + 1;   // 64-row q tile covers k tiles 0..qt

    auto prefetch_kv = [&](int kt, int stage) {
        const int k0 = kt * TKN;
        const uint32_t st = sb + FKV_BASE + stage * KV_STAGE;
        for (int i = tid; i < TKN * 16; i += 128) {
            const int r = i >> 4, v = i & 15;
            const size_t g = kvbase + (size_t)(k0 + r) * D_MODEL + v * 8;
            const uint32_t so = (uint32_t)((v >> 3) * 8192)
                              + SW128((uint32_t)(r * 128 + (v & 7) * 16));
            cpasync16(st + so,         Kh + g);
            cpasync16(st + 16384 + so, Vh + g);
        }
    };

    // ---- load Q tile (hi+lo), subtiles split at d=64 ----
    for (int i = tid; i < TQF * 16; i += 128) {
        const int r = i >> 4, v = i & 15;
        const uint32_t so = (uint32_t)((v >> 3) * 8192)
                          + SW128((uint32_t)(r * 128 + (v & 7) * 16));
        *(uint4*)(smf + FQ_BASE + so) =
            *(const uint4*)(Qh + qbase + (size_t)r * D_MODEL + v * 8);
        *(uint4*)(smf + FQ_LO + so) =
            *(const uint4*)(Ql + qbase + (size_t)r * D_MODEL + v * 8);
    }
    prefetch_kv(0, 0);
    CP_COMMIT();

    const int wm = wid * 16;
    const int a_row = wm + (lane & 15);
    const int a_kh  = (lane >> 4) * 8;

    float oacc[16][4] = {};
    float m0 = -INFINITY, m1 = -INFINITY, l0 = 0.f, l1 = 0.f;

    for (int kt = 0; kt < nkt; kt++) {
        const int k0 = kt * TKN;
        CP_WAIT0();            // stage kt data (only group outstanding)
        __syncthreads();       // also: all warps done reading the other stage
        if (kt + 1 < nkt) { prefetch_kv(kt + 1, (kt + 1) & 1); CP_COMMIT(); }
        const uint32_t st = sb + FKV_BASE + (kt & 1) * KV_STAGE;

        // ---- S = Q K^T (2-term: Qh*Kh + Ql*Kh) ----
        float sacc[8][4] = {};
#pragma unroll
        for (int s = 0; s < 8; s++) {
            const int sub = s >> 2, kb = (s & 3) * 16;
            const uint32_t qoff = (uint32_t)(sub * 8192) +
                SW128((uint32_t)(a_row * 128 + (kb + a_kh) * 2));
            uint32_t qhf[4], qlf[4], kf[8][2];
            ldsm4(qhf, sb + FQ_BASE + qoff);
            ldsm4(qlf, sb + FQ_LO + qoff);
#pragma unroll
            for (int p = 0; p < 4; p++) {
                uint32_t r[4];
                const int jr = (p * 2 + (lane >> 4)) * 8 + (lane & 7);
                ldsm4(r, st + sub * 8192 +
                      SW128((uint32_t)(jr * 128 + (kb + ((lane >> 3) & 1) * 8) * 2)));
                kf[p * 2 + 0][0] = r[0]; kf[p * 2 + 0][1] = r[1];
                kf[p * 2 + 1][0] = r[2]; kf[p * 2 + 1][1] = r[3];
            }
#pragma unroll
            for (int j = 0; j < 8; j++) mma16816(sacc[j], qhf, kf[j]);
#pragma unroll
            for (int j = 0; j < 8; j++) mma16816(sacc[j], qlf, kf[j]);
        }

        // ---- scale (base-2) + causal mask ----
        const bool needmask = (k0 + TKN - 1) > (q0 + wm);
        const int rl = lane >> 2, cl = (lane & 3) * 2;
#pragma unroll
        for (int j = 0; j < 8; j++)
#pragma unroll
            for (int e = 0; e < 4; e++) {
                float v = sacc[j][e] * C2;
                if (needmask) {
                    const int colg = k0 + 8 * j + cl + (e & 1);
                    const int rowg = q0 + wm + rl + (e >> 1) * 8;
                    if (colg > rowg) v = -INFINITY;
                }
                sacc[j][e] = v;
            }

        // ---- online softmax: max reduce (critical), exp, rescale ----
        float mt0 = -INFINITY, mt1 = -INFINITY;
#pragma unroll
        for (int j = 0; j < 8; j++) {
            mt0 = fmaxf(mt0, fmaxf(sacc[j][0], sacc[j][1]));
            mt1 = fmaxf(mt1, fmaxf(sacc[j][2], sacc[j][3]));
        }
        mt0 = fmaxf(mt0, __shfl_xor_sync(0xFFFFFFFFu, mt0, 1));
        mt0 = fmaxf(mt0, __shfl_xor_sync(0xFFFFFFFFu, mt0, 2));
        mt1 = fmaxf(mt1, __shfl_xor_sync(0xFFFFFFFFu, mt1, 1));
        mt1 = fmaxf(mt1, __shfl_xor_sync(0xFFFFFFFFu, mt1, 2));
        const float mn0 = fmaxf(m0, mt0), mn1 = fmaxf(m1, mt1);
        const float al0 = fexp2(m0 - mn0), al1 = fexp2(m1 - mn1);
        float s0 = 0.f, s1 = 0.f;
#pragma unroll
        for (int j = 0; j < 8; j++) {
            sacc[j][0] = fexp2(sacc[j][0] - mn0); s0 += sacc[j][0];
            sacc[j][1] = fexp2(sacc[j][1] - mn0); s0 += sacc[j][1];
            sacc[j][2] = fexp2(sacc[j][2] - mn1); s1 += sacc[j][2];
            sacc[j][3] = fexp2(sacc[j][3] - mn1); s1 += sacc[j][3];
        }
#pragma unroll
        for (int j = 0; j < 16; j++) {
            oacc[j][0] *= al0; oacc[j][1] *= al0;
            oacc[j][2] *= al1; oacc[j][3] *= al1;
        }

        // ---- O += P V (2-term: Ph*Vh + Pl*Vh), V^T via ldmatrix.trans ----
#pragma unroll
        for (int s2 = 0; s2 < 4; s2++) {
            uint32_t ph[4], pl[4];
            split2h(sacc[2 * s2][0],     sacc[2 * s2][1],     ph[0], pl[0]);
            split2h(sacc[2 * s2][2],     sacc[2 * s2][3],     ph[1], pl[1]);
            split2h(sacc[2 * s2 + 1][0], sacc[2 * s2 + 1][1], ph[2], pl[2]);
            split2h(sacc[2 * s2 + 1][2], sacc[2 * s2 + 1][3], ph[3], pl[3]);
            const int vrow = 16 * s2 + ((lane >> 3) & 1) * 8 + (lane & 7);
#pragma unroll
            for (int p = 0; p < 8; p++) {
                const uint32_t voff = (uint32_t)((p >> 2) * 8192) +
                    SW128((uint32_t)(vrow * 128 + 32 * (p & 3) + (lane >> 4) * 16));
                uint32_t r[4];
                ldsm4t(r, st + 16384 + voff);
                uint32_t b0[2] = { r[0], r[1] }, b1[2] = { r[2], r[3] };
                mma16816(oacc[2 * p],     ph, b0);
                mma16816(oacc[2 * p + 1], ph, b1);
                mma16816(oacc[2 * p],     pl, b0);
                mma16816(oacc[2 * p + 1], pl, b1);
            }
        }

        // ---- deferred: sum reduce + l/m update (off the PV critical path) ----
        s0 += __shfl_xor_sync(0xFFFFFFFFu, s0, 1);
        s0 += __shfl_xor_sync(0xFFFFFFFFu, s0, 2);
        s1 += __shfl_xor_sync(0xFFFFFFFFu, s1, 1);
        s1 += __shfl_xor_sync(0xFFFFFFFFu, s1, 2);
        l0 = l0 * al0 + s0;
        l1 = l1 * al1 + s1;
        m0 = mn0; m1 = mn1;
    }

    // ---- epilogue: normalize, round to fp16, store CTX ----
    const float li0 = 1.f / l0, li1 = 1.f / l1;
    const int r0 = q0 + wm + (lane >> 2);
    const int cbase = h * HEAD_DIM + (lane & 3) * 2;
#pragma unroll
    for (int j = 0; j < 16; j++) {
        const size_t o0 = ((size_t)(b * SEQ + r0)) * D_MODEL + cbase + 8 * j;
        const size_t o1 = ((size_t)(b * SEQ + r0 + 8)) * D_MODEL + cbase + 8 * j;
        *(uint32_t*)&Ch[o0] = pack2h(oacc[j][0] * li0, oacc[j][1] * li0);
        *(uint32_t*)&Ch[o1] = pack2h(oacc[j][2] * li1, oacc[j][3] * li1);
    }
}

// ============================================================================
// launch
// ============================================================================
extern "C" void kernel_launch(void* const* d_in, const int* in_sizes, int n_in,
                              void* d_out, int out_size)
{
    const float* x  = (const float*)d_in[0];
    const float* wq = (const float*)d_in[1];
    const float* wk = (const float*)d_in[2];
    const float* wv = (const float*)d_in[3];
    const float* wo = (const float*)d_in[4];
    float* out = (float*)d_out;

    __half *xh, *xl, *wqh, *wkh, *wvh, *woh;
    __half *Qh, *Ql, *Kh, *Vh, *Ch;
    cudaGetSymbolAddress((void**)&xh, g_xh);
    cudaGetSymbolAddress((void**)&xl, g_xl);
    cudaGetSymbolAddress((void**)&wqh, g_wqh);
    cudaGetSymbolAddress((void**)&wkh, g_wkh);
    cudaGetSymbolAddress((void**)&wvh, g_wvh);
    cudaGetSymbolAddress((void**)&woh, g_woh);
    cudaGetSymbolAddress((void**)&Qh, g_Qh);
    cudaGetSymbolAddress((void**)&Ql, g_Ql);
    cudaGetSymbolAddress((void**)&Kh, g_Kh);
    cudaGetSymbolAddress((void**)&Vh, g_Vh);
    cudaGetSymbolAddress((void**)&Ch, g_Ch);

    cudaFuncSetAttribute(gemm_qkv_kernel,
                         cudaFuncAttributeMaxDynamicSharedMemorySize, GEMM_SMEM);
    cudaFuncSetAttribute(gemm_o_kernel,
                         cudaFuncAttributeMaxDynamicSharedMemorySize, GEMM_SMEM);
    cudaFuncSetAttribute(flash_mma_kernel,
                         cudaFuncAttributeMaxDynamicSharedMemorySize, FLASH_SMEM);

    const int nw4 = D_MODEL * D_MODEL / 4;
    dim3 gg(D_MODEL / 128, M_TOTAL / 128);   // (16, 32)

    prep_kernel<<<dim3((nw4 + 255) / 256, 6), 256>>>(
        (const float4*)x, (const float4*)wq, (const float4*)wk,
        (const float4*)wv, (const float4*)wo,
        (uint2*)xh, (uint2*)xl, (uint2*)wqh, (uint2*)wkh,
        (uint2*)wvh, (uint2*)woh, nw4);

    gemm_qkv_kernel<<<dim3(gg.x, gg.y, 3), 128, GEMM_SMEM>>>(
        xh, xl, wqh, wkh, wvh, Qh, Ql, Kh, Vh);

    flash_mma_kernel<<<dim3(BATCH * NUM_HEADS, SEQ / TQF), 128, FLASH_SMEM>>>(
        Qh, Ql, Kh, Vh, Ch);

    gemm_o_kernel<<<gg, 128, GEMM_SMEM>>>(Ch, woh, out);
}

// round 17
// speedup vs baseline: 1.6167x; 1.0520x over previous
#include <cuda_runtime.h>
#include <cuda_fp16.h>
#include <cstdint>
#include <math.h>

#define D_MODEL   2048
#define NUM_HEADS 16
#define HEAD_DIM  128
#define BATCH     2
#define SEQ       2048
#define M_TOTAL   (BATCH * SEQ)   // 4096

// ---------------- scratch (static device globals: no allocation allowed) ----
__device__ __half g_xh[M_TOTAL * D_MODEL];
__device__ __half g_xl[M_TOTAL * D_MODEL];
__device__ __half g_wqh[D_MODEL * D_MODEL];
__device__ __half g_wkh[D_MODEL * D_MODEL];
__device__ __half g_wvh[D_MODEL * D_MODEL];
__device__ __half g_woh[D_MODEL * D_MODEL];
__device__ __half g_Qh[M_TOTAL * D_MODEL];
__device__ __half g_Ql[M_TOTAL * D_MODEL];
__device__ __half g_Kh[M_TOTAL * D_MODEL];
__device__ __half g_Vh[M_TOTAL * D_MODEL];
__device__ __half g_Ch[M_TOTAL * D_MODEL];

// ============================================================================
// helpers
// ============================================================================
__device__ __forceinline__ uint32_t smem_u32(const void* p) {
    uint32_t a;
    asm("{ .reg .u64 t; cvta.to.shared.u64 t, %1; cvt.u32.u64 %0, t; }"
        : "=r"(a) : "l"(p));
    return a;
}
#define SW128(o) ((o) ^ (((o) >> 3) & 0x70))

__device__ __forceinline__ void ldsm4(uint32_t* r, uint32_t addr) {
    asm volatile("ldmatrix.sync.aligned.m8n8.x4.shared.b16 {%0,%1,%2,%3}, [%4];"
                 : "=r"(r[0]), "=r"(r[1]), "=r"(r[2]), "=r"(r[3]) : "r"(addr));
}
__device__ __forceinline__ void ldsm4t(uint32_t* r, uint32_t addr) {
    asm volatile("ldmatrix.sync.aligned.m8n8.x4.trans.shared.b16 {%0,%1,%2,%3}, [%4];"
                 : "=r"(r[0]), "=r"(r[1]), "=r"(r[2]), "=r"(r[3]) : "r"(addr));
}
__device__ __forceinline__ void mma16816(float* d, const uint32_t* a,
                                         const uint32_t* b) {
    asm volatile(
        "mma.sync.aligned.m16n8k16.row.col.f32.f16.f16.f32 "
        "{%0,%1,%2,%3}, {%4,%5,%6,%7}, {%8,%9}, {%0,%1,%2,%3};"
        : "+f"(d[0]), "+f"(d[1]), "+f"(d[2]), "+f"(d[3])
        : "r"(a[0]), "r"(a[1]), "r"(a[2]), "r"(a[3]), "r"(b[0]), "r"(b[1]));
}
__device__ __forceinline__ void cpasync16(uint32_t dst, const void* src) {
    asm volatile("cp.async.cg.shared.global [%0], [%1], 16;"
                 :: "r"(dst), "l"(src) : "memory");
}
#define CP_COMMIT() asm volatile("cp.async.commit_group;" ::: "memory")
#define CP_WAIT2()  asm volatile("cp.async.wait_group 2;" ::: "memory")
#define CP_WAIT1()  asm volatile("cp.async.wait_group 1;" ::: "memory")
#define CP_WAIT0()  asm volatile("cp.async.wait_group 0;" ::: "memory")

// fp32 pair -> fp16x2 hi + fp16x2 lo (residual)
__device__ __forceinline__ void split2h(float a, float b, uint32_t& hi, uint32_t& lo) {
    __half2 h = __floats2half2_rn(a, b);
    hi = *(uint32_t*)&h;
    float ra = a - __half2float(h.x);
    float rb = b - __half2float(h.y);
    __half2 l = __floats2half2_rn(ra, rb);
    lo = *(uint32_t*)&l;
}
__device__ __forceinline__ uint32_t pack2h(float a, float b) {
    __half2 h = __floats2half2_rn(a, b);
    return *(uint32_t*)&h;
}

// fast 2^y on the FMA/ALU pipes (no MUFU). y <= ~0; -inf -> 0.
__device__ __forceinline__ float fexp2(float y) {
    y = fmaxf(y, -120.f);
    const float t = y + 12582912.f;          // 1.5*2^23: round(y) in mantissa
    const int   i = __float_as_int(t);
    const float f = y - (t - 12582912.f);    // f in [-0.5, 0.5]
    float p = 1.33335581e-3f;
    p = fmaf(p, f, 9.61812910e-3f);
    p = fmaf(p, f, 5.55041087e-2f);
    p = fmaf(p, f, 2.40226507e-1f);
    p = fmaf(p, f, 6.93147181e-1f);
    p = fmaf(p, f, 1.0f);
    return __int_as_float(__float_as_int(p) + (i << 23));
}

// ============================================================================
// prep: weight rounding (y=0..3) + x hi/lo split (y=4,5), one launch
// ============================================================================
__global__ __launch_bounds__(256)
void prep_kernel(const float4* __restrict__ x,
                 const float4* __restrict__ wq, const float4* __restrict__ wk,
                 const float4* __restrict__ wv, const float4* __restrict__ wo,
                 uint2* xh, uint2* xl, uint2* qh, uint2* kh, uint2* vh, uint2* oh,
                 int nw4)
{
    int i = blockIdx.x * blockDim.x + threadIdx.x;
    if (i >= nw4) return;
    const int y = blockIdx.y;
    if (y < 4) {
        const float4* s; uint2* h;
        switch (y) {
            case 0:  s = wq; h = qh; break;
            case 1:  s = wk; h = kh; break;
            case 2:  s = wv; h = vh; break;
            default: s = wo; h = oh; break;
        }
        float4 v = s[i];
        uint2 ho;
        ho.x = pack2h(v.x, v.y);
        ho.y = pack2h(v.z, v.w);
        h[i] = ho;
    } else {
        const int idx = i + (y - 4) * nw4;   // x has 2*nw4 float4s
        float4 v = x[idx];
        uint2 ho, lv;
        split2h(v.x, v.y, ho.x, lv.x);
        split2h(v.z, v.w, ho.y, lv.y);
        xh[idx] = ho;
        xl[idx] = lv;
    }
}

// ============================================================================
// Tensor-core GEMM (NT) body — R12/R14 proven structure (two syncs per chunk,
// prefetch issued BEFORE the cp.async wait). DO NOT restructure (R13 lesson).
//   NTERMS=2: C ~= Ah*Bh + Al*Bh ; NTERMS=1: C ~= Ah*Bh (fp32 accum)
// CTA 128x128, K chunk 64. 4 warps (128 thr), warp tile 64x64, 2 CTAs/SM.
// MODE: 0 = fp32 C, 1 = split hi/lo fp16, 2 = rounded fp16
// ============================================================================
#define TKF 64
#define NCHUNK (D_MODEL / TKF)     // 32

template<int NTERMS, int MODE, int NSTAGES>
__device__ __forceinline__
void gemm_body(const __half* __restrict__ Ah,
               const __half* __restrict__ Al,
               const __half* __restrict__ Bh,
               float* __restrict__ C,
               __half* __restrict__ Ch,
               __half* __restrict__ Cl,
               char* smc)
{
    constexpr int NT = NTERMS + 1;               // tiles per stage
    constexpr uint32_t STAGE = (uint32_t)NT * 16384u;
    constexpr uint32_t AL_OFF = 16384u;
    constexpr uint32_t B_OFF  = (uint32_t)(NT - 1) * 16384u;

    const uint32_t sb = smem_u32(smc);
    const int tid  = threadIdx.x;
    const int wid  = tid >> 5;
    const int lane = tid & 31;
    const int bN = blockIdx.x * 128;
    const int bM = blockIdx.y * 128;
    const int wm = (wid & 1) * 64;
    const int wn = (wid >> 1) * 64;

    const int a_row = wm + (lane & 15);
    const int a_kh  = (lane >> 4) * 8;
    const int b_jg  = (lane >> 4);
    const int b_kh  = ((lane >> 3) & 1) * 8;
    const int b_r8  = lane & 7;

    const __half* srcs[3];
    srcs[0] = Ah + (size_t)bM * D_MODEL;
    srcs[1] = (NTERMS == 2) ? (Al + (size_t)bM * D_MODEL)
                            : (Bh + (size_t)bN * D_MODEL);
    srcs[2] = Bh + (size_t)bN * D_MODEL;

    auto prefetch = [&](int c, int stage) {
        const int k0 = c * TKF;
        const uint32_t base = sb + stage * STAGE;
#pragma unroll
        for (int t = 0; t < NT; t++) {
            const __half* s = srcs[t] + k0;
#pragma unroll
            for (int it = 0; it < 8; it++) {
                const int vec = tid + it * 128;
                const int r = vec >> 3, v = vec & 7;
                cpasync16(base + t * 16384 + SW128((uint32_t)(r * 128 + v * 16)),
                          s + (size_t)r * D_MODEL + v * 8);
            }
        }
    };

    float acc[4][8][4] = {};   // warp 64x64: [m-frag][n-frag][4]

    prefetch(0, 0); CP_COMMIT();
    if (NSTAGES == 3) { prefetch(1, 1); CP_COMMIT(); }

    for (int c = 0; c < NCHUNK; c++) {
        if (NSTAGES == 3) {
            if (c + 2 < NCHUNK)      { prefetch(c + 2, (c + 2) % 3); CP_COMMIT(); CP_WAIT2(); }
            else if (c + 1 < NCHUNK) { CP_WAIT1(); }
            else                     { CP_WAIT0(); }
        } else {
            if (c + 1 < NCHUNK) { prefetch(c + 1, (c + 1) & 1); CP_COMMIT(); CP_WAIT1(); }
            else                { CP_WAIT0(); }
        }
        __syncthreads();

        const uint32_t st = sb + (c % NSTAGES) * STAGE;
#pragma unroll
        for (int ks = 0; ks < 4; ks++) {
            const int k16 = ks * 16;
            uint32_t ahf[4][4], bf[8][2];
#pragma unroll
            for (int i = 0; i < 4; i++)
                ldsm4(ahf[i], st +
                      SW128((uint32_t)((a_row + i * 16) * 128 + (k16 + a_kh) * 2)));
#pragma unroll
            for (int p = 0; p < 4; p++) {
                uint32_t r[4];
                const int jr = wn + (p * 2 + b_jg) * 8 + b_r8;
                ldsm4(r, st + B_OFF + SW128((uint32_t)(jr * 128 + (k16 + b_kh) * 2)));
                bf[p * 2 + 0][0] = r[0]; bf[p * 2 + 0][1] = r[1];
                bf[p * 2 + 1][0] = r[2]; bf[p * 2 + 1][1] = r[3];
            }
#pragma unroll
            for (int i = 0; i < 4; i++)
#pragma unroll
                for (int j = 0; j < 8; j++)
                    mma16816(acc[i][j], ahf[i], bf[j]);
            if (NTERMS == 2) {
                uint32_t alf[4][4];
#pragma unroll
                for (int i = 0; i < 4; i++)
                    ldsm4(alf[i], st + AL_OFF +
                          SW128((uint32_t)((a_row + i * 16) * 128 + (k16 + a_kh) * 2)));
#pragma unroll
                for (int i = 0; i < 4; i++)
#pragma unroll
                    for (int j = 0; j < 8; j++)
                        mma16816(acc[i][j], alf[i], bf[j]);
            }
        }
        __syncthreads();
    }

    const int er = bM + wm + (lane >> 2);
    const int ec = bN + wn + (lane & 3) * 2;
#pragma unroll
    for (int i = 0; i < 4; i++)
#pragma unroll
        for (int j = 0; j < 8; j++) {
            const size_t o0 = (size_t)(er + i * 16) * D_MODEL + ec + j * 8;
            const size_t o1 = (size_t)(er + i * 16 + 8) * D_MODEL + ec + j * 8;
            if (MODE == 0) {
                *(float2*)&C[o0] = make_float2(acc[i][j][0], acc[i][j][1]);
                *(float2*)&C[o1] = make_float2(acc[i][j][2], acc[i][j][3]);
            } else if (MODE == 1) {
                uint32_t h, l;
                split2h(acc[i][j][0], acc[i][j][1], h, l);
                *(uint32_t*)&Ch[o0] = h; *(uint32_t*)&Cl[o0] = l;
                split2h(acc[i][j][2], acc[i][j][3], h, l);
                *(uint32_t*)&Ch[o1] = h; *(uint32_t*)&Cl[o1] = l;
            } else {
                *(uint32_t*)&Ch[o0] = pack2h(acc[i][j][0], acc[i][j][1]);
                *(uint32_t*)&Ch[o1] = pack2h(acc[i][j][2], acc[i][j][3]);
            }
        }
}

#define GEMM_SMEM 98304   // 2-term 2-stage = 2*49152; 1-term 3-stage = 3*32768

// fused Q/K/V projections in ONE launch (z=0 Q 2-term, z=1 K, z=2 V 1-term)
__global__ __launch_bounds__(128, 2)
void gemm_qkv_kernel(const __half* __restrict__ xh, const __half* __restrict__ xl,
                     const __half* __restrict__ wqh,
                     const __half* __restrict__ wkh,
                     const __half* __restrict__ wvh,
                     __half* __restrict__ Qh, __half* __restrict__ Ql,
                     __half* __restrict__ Kh, __half* __restrict__ Vh)
{
    extern __shared__ char smc[];
    if (blockIdx.z == 0)
        gemm_body<2, 1, 2>(xh, xl, wqh, nullptr, Qh, Ql, smc);
    else if (blockIdx.z == 1)
        gemm_body<1, 2, 3>(xh, nullptr, wkh, nullptr, Kh, nullptr, smc);
    else
        gemm_body<1, 2, 3>(xh, nullptr, wvh, nullptr, Vh, nullptr, smc);
}

// O projection: 1-term input, fp32 output
__global__ __launch_bounds__(128, 2)
void gemm_o_kernel(const __half* __restrict__ Ch, const __half* __restrict__ woh,
                   float* __restrict__ C)
{
    extern __shared__ char smc[];
    gemm_body<1, 0, 3>(Ch, nullptr, woh, C, nullptr, nullptr, smc);
}

// ============================================================================
// Causal flash attention: fp16 QK 2-term (Qh,Ql vs Kh), PV 1-TERM (Ph*Vh;
// Pl dropped — its correction is below the fp16 CTX-rounding floor).
// base-2 softmax on FMA pipe, cp.async double-buffered K/V.
// CTA = 64 q-rows, 4 warps, 96KB smem, 2 CTAs/SM; deferred l-update.
// ============================================================================
#define TQF 64
#define TKN 64
#define FQ_BASE  0
#define FQ_LO    16384
#define FKV_BASE 32768
#define KV_STAGE 32768
#define FLASH_SMEM (FKV_BASE + 2 * KV_STAGE)   // 98304

__global__ __launch_bounds__(128, 2)
void flash_mma_kernel(const __half* __restrict__ Qh, const __half* __restrict__ Ql,
                      const __half* __restrict__ Kh, const __half* __restrict__ Vh,
                      __half* __restrict__ Ch)
{
    extern __shared__ char smf[];
    const uint32_t sb = smem_u32(smf);
    const int tid  = threadIdx.x;
    const int wid  = tid >> 5;
    const int lane = tid & 31;

    const int bh = blockIdx.x;
    const int qt = (int)(gridDim.y - 1) - (int)blockIdx.y;   // heavy-first
    const int b  = bh >> 4;
    const int h  = bh & 15;
    const int q0 = qt * TQF;
    const float C2 = 0.08838834764831845f * 1.4426950408889634f; // scale*log2e

    const size_t qbase  = ((size_t)(b * SEQ + q0)) * D_MODEL + h * HEAD_DIM;
    const size_t kvbase = ((size_t)(b * SEQ)) * D_MODEL + h * HEAD_DIM;

    const int nkt = qt + 1;   // 64-row q tile covers k tiles 0..qt

    auto prefetch_kv = [&](int kt, int stage) {
        const int k0 = kt * TKN;
        const uint32_t st = sb + FKV_BASE + stage * KV_STAGE;
        for (int i = tid; i < TKN * 16; i += 128) {
            const int r = i >> 4, v = i & 15;
            const size_t g = kvbase + (size_t)(k0 + r) * D_MODEL + v * 8;
            const uint32_t so = (uint32_t)((v >> 3) * 8192)
                              + SW128((uint32_t)(r * 128 + (v & 7) * 16));
            cpasync16(st + so,         Kh + g);
            cpasync16(st + 16384 + so, Vh + g);
        }
    };

    // ---- load Q tile (hi+lo), subtiles split at d=64 ----
    for (int i = tid; i < TQF * 16; i += 128) {
        const int r = i >> 4, v = i & 15;
        const uint32_t so = (uint32_t)((v >> 3) * 8192)
                          + SW128((uint32_t)(r * 128 + (v & 7) * 16));
        *(uint4*)(smf + FQ_BASE + so) =
            *(const uint4*)(Qh + qbase + (size_t)r * D_MODEL + v * 8);
        *(uint4*)(smf + FQ_LO + so) =
            *(const uint4*)(Ql + qbase + (size_t)r * D_MODEL + v * 8);
    }
    prefetch_kv(0, 0);
    CP_COMMIT();

    const int wm = wid * 16;
    const int a_row = wm + (lane & 15);
    const int a_kh  = (lane >> 4) * 8;

    float oacc[16][4] = {};
    float m0 = -INFINITY, m1 = -INFINITY, l0 = 0.f, l1 = 0.f;

    for (int kt = 0; kt < nkt; kt++) {
        const int k0 = kt * TKN;
        CP_WAIT0();            // stage kt data (only group outstanding)
        __syncthreads();       // also: all warps done reading the other stage
        if (kt + 1 < nkt) { prefetch_kv(kt + 1, (kt + 1) & 1); CP_COMMIT(); }
        const uint32_t st = sb + FKV_BASE + (kt & 1) * KV_STAGE;

        // ---- S = Q K^T (2-term: Qh*Kh + Ql*Kh) ----
        float sacc[8][4] = {};
#pragma unroll
        for (int s = 0; s < 8; s++) {
            const int sub = s >> 2, kb = (s & 3) * 16;
            const uint32_t qoff = (uint32_t)(sub * 8192) +
                SW128((uint32_t)(a_row * 128 + (kb + a_kh) * 2));
            uint32_t qhf[4], qlf[4], kf[8][2];
            ldsm4(qhf, sb + FQ_BASE + qoff);
            ldsm4(qlf, sb + FQ_LO + qoff);
#pragma unroll
            for (int p = 0; p < 4; p++) {
                uint32_t r[4];
                const int jr = (p * 2 + (lane >> 4)) * 8 + (lane & 7);
                ldsm4(r, st + sub * 8192 +
                      SW128((uint32_t)(jr * 128 + (kb + ((lane >> 3) & 1) * 8) * 2)));
                kf[p * 2 + 0][0] = r[0]; kf[p * 2 + 0][1] = r[1];
                kf[p * 2 + 1][0] = r[2]; kf[p * 2 + 1][1] = r[3];
            }
#pragma unroll
            for (int j = 0; j < 8; j++) mma16816(sacc[j], qhf, kf[j]);
#pragma unroll
            for (int j = 0; j < 8; j++) mma16816(sacc[j], qlf, kf[j]);
        }

        // ---- scale (base-2) + causal mask ----
        const bool needmask = (k0 + TKN - 1) > (q0 + wm);
        const int rl = lane >> 2, cl = (lane & 3) * 2;
#pragma unroll
        for (int j = 0; j < 8; j++)
#pragma unroll
            for (int e = 0; e < 4; e++) {
                float v = sacc[j][e] * C2;
                if (needmask) {
                    const int colg = k0 + 8 * j + cl + (e & 1);
                    const int rowg = q0 + wm + rl + (e >> 1) * 8;
                    if (colg > rowg) v = -INFINITY;
                }
                sacc[j][e] = v;
            }

        // ---- online softmax: max reduce (critical), exp, rescale ----
        float mt0 = -INFINITY, mt1 = -INFINITY;
#pragma unroll
        for (int j = 0; j < 8; j++) {
            mt0 = fmaxf(mt0, fmaxf(sacc[j][0], sacc[j][1]));
            mt1 = fmaxf(mt1, fmaxf(sacc[j][2], sacc[j][3]));
        }
        mt0 = fmaxf(mt0, __shfl_xor_sync(0xFFFFFFFFu, mt0, 1));
        mt0 = fmaxf(mt0, __shfl_xor_sync(0xFFFFFFFFu, mt0, 2));
        mt1 = fmaxf(mt1, __shfl_xor_sync(0xFFFFFFFFu, mt1, 1));
        mt1 = fmaxf(mt1, __shfl_xor_sync(0xFFFFFFFFu, mt1, 2));
        const float mn0 = fmaxf(m0, mt0), mn1 = fmaxf(m1, mt1);
        const float al0 = fexp2(m0 - mn0), al1 = fexp2(m1 - mn1);
        float s0 = 0.f, s1 = 0.f;
#pragma unroll
        for (int j = 0; j < 8; j++) {
            sacc[j][0] = fexp2(sacc[j][0] - mn0); s0 += sacc[j][0];
            sacc[j][1] = fexp2(sacc[j][1] - mn0); s0 += sacc[j][1];
            sacc[j][2] = fexp2(sacc[j][2] - mn1); s1 += sacc[j][2];
            sacc[j][3] = fexp2(sacc[j][3] - mn1); s1 += sacc[j][3];
        }
#pragma unroll
        for (int j = 0; j < 16; j++) {
            oacc[j][0] *= al0; oacc[j][1] *= al0;
            oacc[j][2] *= al1; oacc[j][3] *= al1;
        }

        // ---- O += P V (1-TERM: Ph*Vh), V^T via ldmatrix.trans ----
#pragma unroll
        for (int s2 = 0; s2 < 4; s2++) {
            uint32_t ph[4];
            ph[0] = pack2h(sacc[2 * s2][0],     sacc[2 * s2][1]);
            ph[1] = pack2h(sacc[2 * s2][2],     sacc[2 * s2][3]);
            ph[2] = pack2h(sacc[2 * s2 + 1][0], sacc[2 * s2 + 1][1]);
            ph[3] = pack2h(sacc[2 * s2 + 1][2], sacc[2 * s2 + 1][3]);
            const int vrow = 16 * s2 + ((lane >> 3) & 1) * 8 + (lane & 7);
#pragma unroll
            for (int p = 0; p < 8; p++) {
                const uint32_t voff = (uint32_t)((p >> 2) * 8192) +
                    SW128((uint32_t)(vrow * 128 + 32 * (p & 3) + (lane >> 4) * 16));
                uint32_t r[4];
                ldsm4t(r, st + 16384 + voff);
                uint32_t b0[2] = { r[0], r[1] }, b1[2] = { r[2], r[3] };
                mma16816(oacc[2 * p],     ph, b0);
                mma16816(oacc[2 * p + 1], ph, b1);
            }
        }

        // ---- deferred: sum reduce + l/m update (off the PV critical path) ----
        s0 += __shfl_xor_sync(0xFFFFFFFFu, s0, 1);
        s0 += __shfl_xor_sync(0xFFFFFFFFu, s0, 2);
        s1 += __shfl_xor_sync(0xFFFFFFFFu, s1, 1);
        s1 += __shfl_xor_sync(0xFFFFFFFFu, s1, 2);
        l0 = l0 * al0 + s0;
        l1 = l1 * al1 + s1;
        m0 = mn0; m1 = mn1;
    }

    // ---- epilogue: normalize, round to fp16, store CTX ----
    const float li0 = 1.f / l0, li1 = 1.f / l1;
    const int r0 = q0 + wm + (lane >> 2);
    const int cbase = h * HEAD_DIM + (lane & 3) * 2;
#pragma unroll
    for (int j = 0; j < 16; j++) {
        const size_t o0 = ((size_t)(b * SEQ + r0)) * D_MODEL + cbase + 8 * j;
        const size_t o1 = ((size_t)(b * SEQ + r0 + 8)) * D_MODEL + cbase + 8 * j;
        *(uint32_t*)&Ch[o0] = pack2h(oacc[j][0] * li0, oacc[j][1] * li0);
        *(uint32_t*)&Ch[o1] = pack2h(oacc[j][2] * li1, oacc[j][3] * li1);
    }
}

// ============================================================================
// launch
// ============================================================================
extern "C" void kernel_launch(void* const* d_in, const int* in_sizes, int n_in,
                              void* d_out, int out_size)
{
    const float* x  = (const float*)d_in[0];
    const float* wq = (const float*)d_in[1];
    const float* wk = (const float*)d_in[2];
    const float* wv = (const float*)d_in[3];
    const float* wo = (const float*)d_in[4];
    float* out = (float*)d_out;

    __half *xh, *xl, *wqh, *wkh, *wvh, *woh;
    __half *Qh, *Ql, *Kh, *Vh, *Ch;
    cudaGetSymbolAddress((void**)&xh, g_xh);
    cudaGetSymbolAddress((void**)&xl, g_xl);
    cudaGetSymbolAddress((void**)&wqh, g_wqh);
    cudaGetSymbolAddress((void**)&wkh, g_wkh);
    cudaGetSymbolAddress((void**)&wvh, g_wvh);
    cudaGetSymbolAddress((void**)&woh, g_woh);
    cudaGetSymbolAddress((void**)&Qh, g_Qh);
    cudaGetSymbolAddress((void**)&Ql, g_Ql);
    cudaGetSymbolAddress((void**)&Kh, g_Kh);
    cudaGetSymbolAddress((void**)&Vh, g_Vh);
    cudaGetSymbolAddress((void**)&Ch, g_Ch);

    cudaFuncSetAttribute(gemm_qkv_kernel,
                         cudaFuncAttributeMaxDynamicSharedMemorySize, GEMM_SMEM);
    cudaFuncSetAttribute(gemm_o_kernel,
                         cudaFuncAttributeMaxDynamicSharedMemorySize, GEMM_SMEM);
    cudaFuncSetAttribute(flash_mma_kernel,
                         cudaFuncAttributeMaxDynamicSharedMemorySize, FLASH_SMEM);

    const int nw4 = D_MODEL * D_MODEL / 4;
    dim3 gg(D_MODEL / 128, M_TOTAL / 128);   // (16, 32)

    prep_kernel<<<dim3((nw4 + 255) / 256, 6), 256>>>(
        (const float4*)x, (const float4*)wq, (const float4*)wk,
        (const float4*)wv, (const float4*)wo,
        (uint2*)xh, (uint2*)xl, (uint2*)wqh, (uint2*)wkh,
        (uint2*)wvh, (uint2*)woh, nw4);

    gemm_qkv_kernel<<<dim3(gg.x, gg.y, 3), 128, GEMM_SMEM>>>(
        xh, xl, wqh, wkh, wvh, Qh, Ql, Kh, Vh);

    flash_mma_kernel<<<dim3(BATCH * NUM_HEADS, SEQ / TQF), 128, FLASH_SMEM>>>(
        Qh, Ql, Kh, Vh, Ch);

    gemm_o_kernel<<<gg, 128, GEMM_SMEM>>>(Ch, woh, out);
}